// round 11
// baseline (speedup 1.0000x reference)
#include <cuda_runtime.h>
#include <cuda_bf16.h>
#include <cstdint>
#include <cstddef>

#define S_DET 725
#define S_ANG 360
#define IMG   512
#define NNZ   8388608LL
#define NB    4

#define ACTN (4ULL*512*512*64)
__device__ float g_A[ACTN];                 // act ping (256B/px hi/lo records)
__device__ float g_B[ACTN];                 // pp accumulator (f32)
__device__ float g_C[ACTN];                 // act pong
__device__ char  g_W[5*25*16384];           // pre-converted weights (swizzled hi/lo)
__device__ float g_filtT[S_DET*S_ANG*4];
__device__ float g_fbpT[IMG*IMG*4];
__device__ float g_fbp[4*IMG*IMG];

__device__ __forceinline__ uint32_t smem_u32(const void* p) {
    uint32_t a;
    asm("{ .reg .u64 t; cvta.to.shared.u64 t, %1; cvt.u32.u64 %0, t; }"
        : "=r"(a) : "l"(p));
    return a;
}
__device__ __forceinline__ uint32_t packbf(float lo, float hi) {
    uint32_t r;
    asm("cvt.rn.bf16x2.f32 %0, %1, %2;" : "=r"(r) : "f"(hi), "f"(lo));
    return r;
}
#define SWZ(o) ((o) ^ (((o) >> 3) & 0x70))

#define CP_ASYNC16(dst_u32, src) \
    asm volatile("cp.async.cg.shared.global [%0], [%1], 16;" :: "r"(dst_u32), "l"(src))
#define CP_COMMIT() asm volatile("cp.async.commit_group;")
#define CP_WAIT0()  asm volatile("cp.async.wait_group 0;")

#define LDSM_X4(r0,r1,r2,r3,addr) \
    asm volatile("ldmatrix.sync.aligned.m8n8.x4.shared.b16 {%0,%1,%2,%3}, [%4];" \
        : "=r"(r0),"=r"(r1),"=r"(r2),"=r"(r3) : "r"(addr))
#define LDSM_X4T(r0,r1,r2,r3,addr) \
    asm volatile("ldmatrix.sync.aligned.m8n8.x4.trans.shared.b16 {%0,%1,%2,%3}, [%4];" \
        : "=r"(r0),"=r"(r1),"=r"(r2),"=r"(r3) : "r"(addr))
#define MMA_BF16(d,a0,a1,a2,a3,b0,b1) \
    asm volatile("mma.sync.aligned.m16n8k16.row.col.f32.bf16.bf16.f32 " \
        "{%0,%1,%2,%3}, {%4,%5,%6,%7}, {%8,%9}, {%0,%1,%2,%3};" \
        : "+f"((d)[0]),"+f"((d)[1]),"+f"((d)[2]),"+f"((d)[3]) \
        : "r"(a0),"r"(a1),"r"(a2),"r"(a3),"r"(b0),"r"(b1))

// smem map: A ping/pong (each: hi 16896 | lo 16896), W ping/pong (hi 8192 | lo 8192)
#define O_BN  0
#define O_A0  1024
#define O_A1  (O_A0 + 33792)     // 34816
#define O_W0  (O_A1 + 33792)     // 68608
#define O_W1  (O_W0 + 16384)     // 84992
#define MMSM  (O_W1 + 16384)     // 101376

// ---------------------------------------------------------------------------
// prep: convert conv weights f32 -> bf16 hi/lo, swizzled panel layout
// ---------------------------------------------------------------------------
__global__ void __launch_bounds__(256) prep_w(
    const float* __restrict__ w, char* __restrict__ gw, int layers)
{
    const int idx = blockIdx.x*blockDim.x + threadIdx.x;
    if (idx >= layers*25*4096) return;
    const int l = idx / 102400, r = idx - l*102400;
    const int tap = r >> 12, e = r & 4095;
    const int ci = e >> 6, co = e & 63;
    const float f = w[(size_t)l*102400 + tap*4096 + ci*64 + co];
    const uint32_t hb = packbf(f, 0.f) & 0xFFFFu;
    const float lf = f - __uint_as_float(hb << 16);
    const uint32_t lb = packbf(lf, 0.f) & 0xFFFFu;
    char* base = gw + (size_t)l*409600 + tap*16384;
    const uint32_t off = SWZ((uint32_t)(ci*128 + co*2));
    *(uint16_t*)(base + off)        = (uint16_t)hb;
    *(uint16_t*)(base + 8192 + off) = (uint16_t)lb;
}

// ---------------------------------------------------------------------------
// conv 5x5 64->64 + BN + ReLU via mma.sync bf16 split; 1-barrier/tap pipeline.
// act records 256B/px [hi 128B | lo 128B]. pp += result (f32).
// CTA: 128 px of row y. 128 threads, 4 warps.
// ---------------------------------------------------------------------------
__global__ void __launch_bounds__(128) conv_mid_mma(
    const char* __restrict__ xact, const char* __restrict__ wconv,
    const float* __restrict__ gamma, const float* __restrict__ beta,
    const float* __restrict__ mean, const float* __restrict__ var,
    char* __restrict__ yact, float* __restrict__ pp, int H, int W)
{
    extern __shared__ char sm[];
    const uint32_t sb = smem_u32(sm);
    const int t = threadIdx.x, lane = t & 31, wid = t >> 5;
    const int b = blockIdx.z, y = blockIdx.y, x0 = blockIdx.x*128;

    float* scp = (float*)(sm + O_BN);
    float* bsp = scp + 64;
    if (t < 64) {
        float s = gamma[t] * rsqrtf(var[t] + 1e-3f);
        scp[t] = s; bsp[t] = beta[t] - mean[t]*s;
    }

    float acc[2][8][4];
    #pragma unroll
    for (int mt = 0; mt < 2; ++mt)
        #pragma unroll
        for (int n = 0; n < 8; ++n)
            acc[mt][n][0] = acc[mt][n][1] = acc[mt][n][2] = acc[mt][n][3] = 0.f;

    const int ar = lane & 15;
    const int ak = (lane >> 4) * 16;
    const int brow = ((lane >> 3) & 1)*8 + (lane & 7);
    const int bnn  = (lane >> 4);

    auto stageA = [&](int dy, int buf) {
        const int yin = y - 2 + dy;
        const bool yok = (unsigned)yin < (unsigned)H;
        const char* xr = xact + ((size_t)b*H + (yok ? yin : 0))*W*256;
        const int abase = buf ? O_A1 : O_A0;
        for (int i = t; i < 2112; i += 128) {
            const int p = i >> 4, j = i & 15;
            const int xin = x0 + p - 2;
            const uint32_t rel = (j < 8 ? 0u : 16896u)
                               + SWZ((uint32_t)(p*128 + (j & 7)*16));
            if (yok && (unsigned)xin < (unsigned)W) {
                CP_ASYNC16(sb + abase + rel,
                           xr + (size_t)xin*256 + (j < 8 ? j*16 : 128 + (j-8)*16));
            } else {
                *(uint4*)(sm + abase + rel) = make_uint4(0,0,0,0);
            }
        }
    };
    auto stageW = [&](int tap) {
        const uint32_t wb = sb + ((tap & 1) ? O_W1 : O_W0);
        const char* src = wconv + (size_t)tap*16384;
        #pragma unroll
        for (int j = 0; j < 8; ++j)
            CP_ASYNC16(wb + (t + j*128)*16, src + (t + j*128)*16);
    };

    // pre-loop: A(dy0) into buf0 and W0, one group
    stageA(0, 0);
    stageW(0);
    CP_COMMIT();

    for (int tap = 0; tap < 25; ++tap) {
        const int dx = tap % 5, dy = tap / 5;
        CP_WAIT0();            // the single in-flight group (copied during tap-1)
        __syncthreads();       // visibility + all buffers' prior readers done
        if (tap < 24) {
            stageW(tap + 1);
            if (dx == 4) stageA(dy + 1, (dy + 1) & 1);
            CP_COMMIT();
        }

        const uint32_t wbuf = sb + ((tap & 1) ? O_W1 : O_W0);
        const uint32_t abuf = sb + ((dy & 1) ? O_A1 : O_A0);
        const int p0 = wid*32 + dx;
        #pragma unroll
        for (int k = 0; k < 4; ++k) {
            uint32_t ah[2][4], al[2][4];
            #pragma unroll
            for (int mt = 0; mt < 2; ++mt) {
                const uint32_t abyte = (uint32_t)((p0 + mt*16 + ar)*128 + k*32 + ak);
                LDSM_X4(ah[mt][0],ah[mt][1],ah[mt][2],ah[mt][3],
                        abuf + SWZ(abyte));
                LDSM_X4(al[mt][0],al[mt][1],al[mt][2],al[mt][3],
                        abuf + 16896 + SWZ(abyte));
            }
            const uint32_t bbyte0 = (uint32_t)((k*16 + brow)*128);
            #pragma unroll
            for (int np = 0; np < 4; ++np) {
                const uint32_t bbyte = SWZ(bbyte0 + (np*2 + bnn)*16);
                uint32_t bh0,bh1,bh2,bh3, bl0,bl1,bl2,bl3;
                LDSM_X4T(bh0,bh1,bh2,bh3, wbuf + bbyte);
                LDSM_X4T(bl0,bl1,bl2,bl3, wbuf + 8192 + bbyte);
                #pragma unroll
                for (int mt = 0; mt < 2; ++mt) {
                    MMA_BF16(acc[mt][np*2],
                             ah[mt][0],ah[mt][1],ah[mt][2],ah[mt][3], bh0,bh1);
                    MMA_BF16(acc[mt][np*2],
                             ah[mt][0],ah[mt][1],ah[mt][2],ah[mt][3], bl0,bl1);
                    MMA_BF16(acc[mt][np*2],
                             al[mt][0],al[mt][1],al[mt][2],al[mt][3], bh0,bh1);
                    MMA_BF16(acc[mt][np*2+1],
                             ah[mt][0],ah[mt][1],ah[mt][2],ah[mt][3], bh2,bh3);
                    MMA_BF16(acc[mt][np*2+1],
                             ah[mt][0],ah[mt][1],ah[mt][2],ah[mt][3], bl2,bl3);
                    MMA_BF16(acc[mt][np*2+1],
                             al[mt][0],al[mt][1],al[mt][2],al[mt][3], bh2,bh3);
                }
            }
        }
    }

    // epilogue: BN + ReLU; write act (hi/lo) + pp += (f32)
    const int r0 = lane >> 2;
    const size_t rowoff = ((size_t)b*H + y)*W;
    #pragma unroll
    for (int mt = 0; mt < 2; ++mt) {
        const int gxa = x0 + wid*32 + mt*16 + r0;
        const int gxb = gxa + 8;
        #pragma unroll
        for (int nt = 0; nt < 8; ++nt) {
            const int co = nt*8 + (lane & 3)*2;
            const float s0 = scp[co], s1 = scp[co+1];
            const float c0 = bsp[co], c1 = bsp[co+1];
            #pragma unroll
            for (int half = 0; half < 2; ++half) {
                const int gx = half ? gxb : gxa;
                if (gx < W) {
                    const float va = fmaxf(fmaf(acc[mt][nt][half*2+0], s0, c0), 0.f);
                    const float vb = fmaxf(fmaf(acc[mt][nt][half*2+1], s1, c1), 0.f);
                    const uint32_t hp = packbf(va, vb);
                    const float la = va - __uint_as_float(hp << 16);
                    const float lb = vb - __uint_as_float(hp & 0xFFFF0000u);
                    const uint32_t lp = packbf(la, lb);
                    char* ab = yact + (rowoff + gx)*256 + co*2;
                    *(uint32_t*)ab         = hp;
                    *(uint32_t*)(ab + 128) = lp;
                    const size_t off = (rowoff + gx)*64 + co;
                    float2 p = *(float2*)(pp + off);
                    p.x += va; p.y += vb;
                    *(float2*)(pp + off) = p;
                }
            }
        }
    }
}

// ---------------------------------------------------------------------------
// conv 5x5, Cin=1 -> Cout=64, +bias, ReLU; writes act (hi/lo) and pp (f32)
// ---------------------------------------------------------------------------
__global__ void __launch_bounds__(256) conv_first(
    const float* __restrict__ x, const float* __restrict__ w,
    const float* __restrict__ bias,
    char* __restrict__ yact, float* __restrict__ pp, int H, int W)
{
    __shared__ float xs[12*12];
    __shared__ float ws[25*64];
    const int t = threadIdx.x;
    const int b = blockIdx.z;
    const int x0 = blockIdx.x*8 - 2, y0 = blockIdx.y*8 - 2;
    const float* xb = x + (size_t)b*H*W;
    if (t < 144) {
        int yy = y0 + t/12, xx = x0 + t%12;
        xs[t] = ((unsigned)yy < (unsigned)H && (unsigned)xx < (unsigned)W)
                ? xb[(size_t)yy*W + xx] : 0.f;
    }
    for (int i = t; i < 1600; i += 256) ws[i] = w[i];
    __syncthreads();

    const int cg = t & 15, pg = t >> 4;
    const int co0 = cg*4;
    int py[4], px[4];
    #pragma unroll
    for (int k = 0; k < 4; ++k) { int p = pg + 16*k; py[k] = p >> 3; px[k] = p & 7; }
    float acc[4][4];
    #pragma unroll
    for (int k = 0; k < 4; ++k)
        #pragma unroll
        for (int j = 0; j < 4; ++j) acc[k][j] = 0.f;

    #pragma unroll
    for (int tap = 0; tap < 25; ++tap) {
        const int dy = tap/5, dx = tap - 5*(tap/5);
        const float4 wv = *(const float4*)(ws + tap*64 + co0);
        #pragma unroll
        for (int k = 0; k < 4; ++k) {
            float a = xs[(py[k]+dy)*12 + px[k]+dx];
            acc[k][0] = fmaf(a, wv.x, acc[k][0]);
            acc[k][1] = fmaf(a, wv.y, acc[k][1]);
            acc[k][2] = fmaf(a, wv.z, acc[k][2]);
            acc[k][3] = fmaf(a, wv.w, acc[k][3]);
        }
    }
    const int gx0 = blockIdx.x*8, gy0 = blockIdx.y*8;
    float bs[4];
    #pragma unroll
    for (int j = 0; j < 4; ++j) bs[j] = bias[co0+j];
    #pragma unroll
    for (int k = 0; k < 4; ++k) {
        int gy = gy0 + py[k], gx = gx0 + px[k];
        if (gy < H && gx < W) {
            float r0 = fmaxf(acc[k][0] + bs[0], 0.f);
            float r1 = fmaxf(acc[k][1] + bs[1], 0.f);
            float r2 = fmaxf(acc[k][2] + bs[2], 0.f);
            float r3 = fmaxf(acc[k][3] + bs[3], 0.f);
            const size_t pix = ((size_t)b*H + gy)*W + gx;
            uint32_t h01 = packbf(r0, r1), h23 = packbf(r2, r3);
            float l0 = r0 - __uint_as_float(h01 << 16);
            float l1 = r1 - __uint_as_float(h01 & 0xFFFF0000u);
            float l2 = r2 - __uint_as_float(h23 << 16);
            float l3 = r3 - __uint_as_float(h23 & 0xFFFF0000u);
            uint32_t lo01 = packbf(l0, l1), lo23 = packbf(l2, l3);
            char* ab = yact + pix*256 + co0*2;
            *(uint2*)ab         = make_uint2(h01, h23);
            *(uint2*)(ab + 128) = make_uint2(lo01, lo23);
            *(float4*)(pp + pix*64 + co0) = make_float4(r0, r1, r2, r3);
        }
    }
}

// ---------------------------------------------------------------------------
__global__ void __launch_bounds__(256) conv_last(
    const float* __restrict__ ppin, const float* __restrict__ w,
    const float* __restrict__ bias, const float* __restrict__ res,
    float* __restrict__ out, int H, int W, float invM)
{
    extern __shared__ float smemf[];
    float* xs = smemf;
    float* ws = smemf + 25600;
    const int t = threadIdx.x;
    const int b = blockIdx.z;
    const int x0 = blockIdx.x*16 - 2, y0 = blockIdx.y*16 - 2;
    const float* xb = ppin + (size_t)b*H*W*64;

    float4* xs4 = (float4*)xs;
    for (int i = t; i < 20*20*16; i += 256) {
        int p = i >> 4, c4 = i & 15;
        int yy = y0 + p/20, xx = x0 + p - 20*(p/20);
        float4 v = make_float4(0.f,0.f,0.f,0.f);
        if ((unsigned)yy < (unsigned)H && (unsigned)xx < (unsigned)W)
            v = *(const float4*)(xb + ((size_t)yy*W + xx)*64 + c4*4);
        xs4[i] = v;
    }
    for (int i = t; i < 1600; i += 256) ws[i] = w[i];
    __syncthreads();

    const int ty = t >> 4, tx = t & 15;
    const int gy = blockIdx.y*16 + ty, gx = blockIdx.x*16 + tx;
    if (gy >= H || gx >= W) return;
    float acc = 0.f;
    for (int tap = 0; tap < 25; ++tap) {
        const int dy = tap/5, dx = tap - 5*(tap/5);
        const float4* xv = (const float4*)(xs + ((ty+dy)*20 + tx+dx)*64);
        const float4* wv = (const float4*)(ws + tap*64);
        #pragma unroll
        for (int c4 = 0; c4 < 16; ++c4) {
            float4 a = xv[c4], q = wv[c4];
            acc = fmaf(a.x, q.x, acc);
            acc = fmaf(a.y, q.y, acc);
            acc = fmaf(a.z, q.z, acc);
            acc = fmaf(a.w, q.w, acc);
        }
    }
    size_t pix = ((size_t)b*H + gy)*W + gx;
    out[pix] = fmaf(acc, invM, bias[0]) + res[pix];
}

// ---------------------------------------------------------------------------
__global__ void __launch_bounds__(736) filter_kernel(
    const float* __restrict__ de_sin, const float* __restrict__ wb,
    float* __restrict__ filtT)
{
    __shared__ float xs[S_DET + S_DET - 1];
    __shared__ float wbs[S_DET];
    const int t = threadIdx.x;
    const int blk = blockIdx.x;
    const int b = blk / S_ANG, ang = blk - b*S_ANG;
    for (int i = t; i < 2*S_DET-1; i += 736) xs[i] = 0.f;
    if (t < S_DET) wbs[t] = wb[t];
    __syncthreads();
    if (t < S_DET)
        xs[362 + t] = de_sin[((size_t)b*S_DET + t)*S_ANG + ang];
    __syncthreads();
    if (t < S_DET) {
        float acc = 0.f;
        #pragma unroll 5
        for (int k = 0; k < S_DET; ++k)
            acc = fmaf(wbs[k], xs[t + k], acc);
        filtT[((size_t)ang*S_DET + t)*4 + b] = acc;
    }
}

// ---------------------------------------------------------------------------
__global__ void __launch_bounds__(256) backproj(
    const float* __restrict__ vals, const int* __restrict__ rows,
    const int* __restrict__ cols, const float4* __restrict__ filtT,
    float* __restrict__ fbpT)
{
    const long long s = ((long long)blockIdx.x*blockDim.x + threadIdx.x) * 16;
    if (s >= NNZ) return;
    int cur = rows[s];
    float a0 = 0.f, a1 = 0.f, a2 = 0.f, a3 = 0.f;
    #pragma unroll 4
    for (int j = 0; j < 16; ++j) {
        const long long i = s + j;
        const int r = rows[i];
        if (r != cur) {
            atomicAdd(&fbpT[(size_t)cur*4+0], a0);
            atomicAdd(&fbpT[(size_t)cur*4+1], a1);
            atomicAdd(&fbpT[(size_t)cur*4+2], a2);
            atomicAdd(&fbpT[(size_t)cur*4+3], a3);
            cur = r; a0 = a1 = a2 = a3 = 0.f;
        }
        const float v = vals[i];
        const float4 f = filtT[cols[i]];
        a0 = fmaf(v, f.x, a0);
        a1 = fmaf(v, f.y, a1);
        a2 = fmaf(v, f.z, a2);
        a3 = fmaf(v, f.w, a3);
    }
    atomicAdd(&fbpT[(size_t)cur*4+0], a0);
    atomicAdd(&fbpT[(size_t)cur*4+1], a1);
    atomicAdd(&fbpT[(size_t)cur*4+2], a2);
    atomicAdd(&fbpT[(size_t)cur*4+3], a3);
}

__global__ void __launch_bounds__(256) fbp_fin(
    const float* __restrict__ fbpT, float* __restrict__ fbp,
    float* __restrict__ out_fbp)
{
    const int i = blockIdx.x*blockDim.x + threadIdx.x;
    if (i >= IMG*IMG) return;
    const float4 v = *(const float4*)(fbpT + (size_t)i*4);
    const float r0 = 4.f*v.x, r1 = 4.f*v.y, r2 = 4.f*v.z, r3 = 4.f*v.w;
    fbp[0*IMG*IMG + i] = r0;  out_fbp[0*IMG*IMG + i] = r0;
    fbp[1*IMG*IMG + i] = r1;  out_fbp[1*IMG*IMG + i] = r1;
    fbp[2*IMG*IMG + i] = r2;  out_fbp[2*IMG*IMG + i] = r2;
    fbp[3*IMG*IMG + i] = r3;  out_fbp[3*IMG*IMG + i] = r3;
}

// ---------------------------------------------------------------------------
extern "C" void kernel_launch(void* const* d_in, const int* in_sizes, int n_in,
                              void* d_out, int out_size)
{
    const float* inputs    = (const float*)d_in[0];
    const float* w_sin1    = (const float*)d_in[1];
    const float* b_sin1    = (const float*)d_in[2];
    const float* w_sin_mid = (const float*)d_in[3];
    const float* sin_gamma = (const float*)d_in[4];
    const float* sin_beta  = (const float*)d_in[5];
    const float* sin_mean  = (const float*)d_in[6];
    const float* sin_var   = (const float*)d_in[7];
    const float* w_sin6    = (const float*)d_in[8];
    const float* b_sin6    = (const float*)d_in[9];
    const float* w_ct1     = (const float*)d_in[10];
    const float* b_ct1     = (const float*)d_in[11];
    const float* w_ct_mid  = (const float*)d_in[12];
    const float* ct_gamma  = (const float*)d_in[13];
    const float* ct_beta   = (const float*)d_in[14];
    const float* ct_mean   = (const float*)d_in[15];
    const float* ct_var    = (const float*)d_in[16];
    const float* w_ct6     = (const float*)d_in[17];
    const float* b_ct6     = (const float*)d_in[18];
    const float* w_b       = (const float*)d_in[19];
    const float* at_vals   = (const float*)d_in[20];
    const int*   at_rows   = (const int*)d_in[21];
    const int*   at_cols   = (const int*)d_in[22];

    float *pA, *pB, *pC, *pFiltT, *pFbpT, *pFbp;
    char* pW;
    cudaGetSymbolAddress((void**)&pA, g_A);
    cudaGetSymbolAddress((void**)&pB, g_B);
    cudaGetSymbolAddress((void**)&pC, g_C);
    cudaGetSymbolAddress((void**)&pW, g_W);
    cudaGetSymbolAddress((void**)&pFiltT, g_filtT);
    cudaGetSymbolAddress((void**)&pFbpT, g_fbpT);
    cudaGetSymbolAddress((void**)&pFbp, g_fbp);

    cudaFuncSetAttribute(conv_mid_mma, cudaFuncAttributeMaxDynamicSharedMemorySize, MMSM);
    cudaFuncSetAttribute(conv_last,    cudaFuncAttributeMaxDynamicSharedMemorySize, 108800);

    float* out_desin = (float*)d_out;
    float* out_img   = out_desin + 4*S_DET*S_ANG;
    float* out_fbp   = out_img + 4*IMG*IMG;

    char* actA = (char*)pA;
    char* actC = (char*)pC;

    // --- sinogram CNN ---
    {
        prep_w<<<(4*25*4096 + 255)/256, 256>>>(w_sin_mid, pW, 4);
        dim3 gs((S_ANG+7)/8, (S_DET+7)/8, NB);
        conv_first<<<gs, 256>>>(inputs, w_sin1, b_sin1, actA, pB, S_DET, S_ANG);
        dim3 gm((S_ANG+127)/128, S_DET, NB);
        char* cur = actA; char* nxt = actC;
        for (int i = 0; i < 4; ++i) {
            conv_mid_mma<<<gm, 128, MMSM>>>(cur, pW + (size_t)i*409600,
                                            sin_gamma + i*64, sin_beta + i*64,
                                            sin_mean + i*64, sin_var + i*64,
                                            nxt, pB, S_DET, S_ANG);
            char* tmp = cur; cur = nxt; nxt = tmp;
        }
        dim3 gs2((S_ANG+15)/16, (S_DET+15)/16, NB);
        conv_last<<<gs2, 256, 108800>>>(pB, w_sin6, b_sin6, inputs, out_desin,
                                        S_DET, S_ANG, 0.25f);
    }

    // --- FBP decode ---
    filter_kernel<<<NB*S_ANG, 736>>>(out_desin, w_b, pFiltT);
    cudaMemsetAsync(pFbpT, 0, (size_t)IMG*IMG*4*sizeof(float));
    backproj<<<(int)(NNZ/16/256), 256>>>(at_vals, at_rows, at_cols,
                                         (const float4*)pFiltT, pFbpT);
    fbp_fin<<<(IMG*IMG+255)/256, 256>>>(pFbpT, pFbp, out_fbp);

    // --- image CNN ---
    {
        prep_w<<<(5*25*4096 + 255)/256, 256>>>(w_ct_mid, pW, 5);
        dim3 gi(IMG/8, IMG/8, NB);
        conv_first<<<gi, 256>>>(pFbp, w_ct1, b_ct1, actA, pB, IMG, IMG);
        dim3 gm(IMG/128, IMG, NB);
        char* cur = actA; char* nxt = actC;
        for (int i = 0; i < 5; ++i) {
            conv_mid_mma<<<gm, 128, MMSM>>>(cur, pW + (size_t)i*409600,
                                            ct_gamma + i*64, ct_beta + i*64,
                                            ct_mean + i*64, ct_var + i*64,
                                            nxt, pB, IMG, IMG);
            char* tmp = cur; cur = nxt; nxt = tmp;
        }
        dim3 gi2(IMG/16, IMG/16, NB);
        conv_last<<<gi2, 256, 108800>>>(pB, w_ct6, b_ct6, pFbp, out_img,
                                        IMG, IMG, 0.2f);
    }
}

// round 12
// speedup vs baseline: 1.0795x; 1.0795x over previous
#include <cuda_runtime.h>
#include <cuda_bf16.h>
#include <cstdint>
#include <cstddef>

#define S_DET 725
#define S_ANG 360
#define IMG   512
#define NNZ   8388608LL
#define NB    4

#define ACTN (4ULL*512*512*64)
__device__ float g_A[ACTN];                 // act ping (256B/px hi/lo records)
__device__ float g_B[ACTN];                 // pp accumulator (f32)
__device__ float g_C[ACTN];                 // act pong
__device__ char  g_W[5*25*16384];           // pre-converted weights (swizzled hi/lo)
__device__ float g_filtT[S_DET*S_ANG*4];
__device__ float g_fbpT[IMG*IMG*4];
__device__ float g_fbp[4*IMG*IMG];

__device__ __forceinline__ uint32_t smem_u32(const void* p) {
    uint32_t a;
    asm("{ .reg .u64 t; cvta.to.shared.u64 t, %1; cvt.u32.u64 %0, t; }"
        : "=r"(a) : "l"(p));
    return a;
}
__device__ __forceinline__ uint32_t packbf(float lo, float hi) {
    uint32_t r;
    asm("cvt.rn.bf16x2.f32 %0, %1, %2;" : "=r"(r) : "f"(hi), "f"(lo));
    return r;
}
#define SWZ(o) ((o) ^ (((o) >> 3) & 0x70))

#define CP_ASYNC16(dst_u32, src) \
    asm volatile("cp.async.cg.shared.global [%0], [%1], 16;" :: "r"(dst_u32), "l"(src))
#define CP_COMMIT() asm volatile("cp.async.commit_group;")
#define CP_WAIT1()  asm volatile("cp.async.wait_group 1;")

#define LDSM_X4(r0,r1,r2,r3,addr) \
    asm volatile("ldmatrix.sync.aligned.m8n8.x4.shared.b16 {%0,%1,%2,%3}, [%4];" \
        : "=r"(r0),"=r"(r1),"=r"(r2),"=r"(r3) : "r"(addr))
#define LDSM_X4T(r0,r1,r2,r3,addr) \
    asm volatile("ldmatrix.sync.aligned.m8n8.x4.trans.shared.b16 {%0,%1,%2,%3}, [%4];" \
        : "=r"(r0),"=r"(r1),"=r"(r2),"=r"(r3) : "r"(addr))
#define MMA_BF16(d,a0,a1,a2,a3,b0,b1) \
    asm volatile("mma.sync.aligned.m16n8k16.row.col.f32.bf16.bf16.f32 " \
        "{%0,%1,%2,%3}, {%4,%5,%6,%7}, {%8,%9}, {%0,%1,%2,%3};" \
        : "+f"((d)[0]),"+f"((d)[1]),"+f"((d)[2]),"+f"((d)[3]) \
        : "r"(a0),"r"(a1),"r"(a2),"r"(a3),"r"(b0),"r"(b1))

// smem map (1024-aligned swizzle regions) — R10 layout
#define O_BN  0
#define O_AH  1024                 // 132*128 = 16896
#define O_AL  18432                // 16896
#define O_W0  35840                // 16384 (hi 8192 | lo 8192)
#define O_W1  52224                // 16384
#define MMSM  68608

// ---------------------------------------------------------------------------
// prep: convert conv weights f32 -> bf16 hi/lo, swizzled panel layout
// ---------------------------------------------------------------------------
__global__ void __launch_bounds__(256) prep_w(
    const float* __restrict__ w, char* __restrict__ gw, int layers)
{
    const int idx = blockIdx.x*blockDim.x + threadIdx.x;
    if (idx >= layers*25*4096) return;
    const int l = idx / 102400, r = idx - l*102400;
    const int tap = r >> 12, e = r & 4095;
    const int ci = e >> 6, co = e & 63;
    const float f = w[(size_t)l*102400 + tap*4096 + ci*64 + co];
    const uint32_t hb = packbf(f, 0.f) & 0xFFFFu;
    const float lf = f - __uint_as_float(hb << 16);
    const uint32_t lb = packbf(lf, 0.f) & 0xFFFFu;
    char* base = gw + (size_t)l*409600 + tap*16384;
    const uint32_t off = SWZ((uint32_t)(ci*128 + co*2));
    *(uint16_t*)(base + off)        = (uint16_t)hb;
    *(uint16_t*)(base + 8192 + off) = (uint16_t)lb;
}

// ---------------------------------------------------------------------------
// conv 5x5 64->64 + BN + ReLU via mma.sync bf16 split (R10 pipeline).
// act records 256B/px [hi 128B | lo 128B]. pp += result (f32).
// CTA: 128 px of row y. 128 threads, 4 warps.
// ---------------------------------------------------------------------------
__global__ void __launch_bounds__(128) conv_mid_mma(
    const char* __restrict__ xact, const char* __restrict__ wconv,
    const float* __restrict__ gamma, const float* __restrict__ beta,
    const float* __restrict__ mean, const float* __restrict__ var,
    char* __restrict__ yact, float* __restrict__ pp, int H, int W)
{
    extern __shared__ char sm[];
    const uint32_t sb = smem_u32(sm);
    const int t = threadIdx.x, lane = t & 31, wid = t >> 5;
    const int b = blockIdx.z, y = blockIdx.y, x0 = blockIdx.x*128;

    float* scp = (float*)(sm + O_BN);
    float* bsp = scp + 64;
    if (t < 64) {
        float s = gamma[t] * rsqrtf(var[t] + 1e-3f);
        scp[t] = s; bsp[t] = beta[t] - mean[t]*s;
    }

    float acc[2][8][4];
    #pragma unroll
    for (int mt = 0; mt < 2; ++mt)
        #pragma unroll
        for (int n = 0; n < 8; ++n)
            acc[mt][n][0] = acc[mt][n][1] = acc[mt][n][2] = acc[mt][n][3] = 0.f;

    const int ar = lane & 15;
    const int ak = (lane >> 4) * 16;
    const int brow = ((lane >> 3) & 1)*8 + (lane & 7);
    const int bnn  = (lane >> 4);

    auto stageA = [&](int dy) {
        const int yin = y - 2 + dy;
        const bool yok = (unsigned)yin < (unsigned)H;
        const char* xr = xact + ((size_t)b*H + (yok ? yin : 0))*W*256;
        for (int i = t; i < 2112; i += 128) {
            const int p = i >> 4, j = i & 15;
            const int xin = x0 + p - 2;
            const uint32_t dst = sb + (j < 8 ? O_AH : O_AL)
                               + SWZ((uint32_t)(p*128 + (j & 7)*16));
            if (yok && (unsigned)xin < (unsigned)W) {
                CP_ASYNC16(dst, xr + (size_t)xin*256 + (j < 8 ? j*16 : 128 + (j-8)*16));
            } else {
                *(uint4*)(sm + (j < 8 ? O_AH : O_AL)
                          + SWZ((uint32_t)(p*128 + (j & 7)*16))) = make_uint4(0,0,0,0);
            }
        }
    };
    auto stageW = [&](int tap) {
        const uint32_t wb = sb + ((tap & 1) ? O_W1 : O_W0);
        const char* src = wconv + (size_t)tap*16384;
        #pragma unroll
        for (int j = 0; j < 8; ++j)
            CP_ASYNC16(wb + (t + j*128)*16, src + (t + j*128)*16);
    };

    // pre-loop: A(dy0) and W0
    stageA(0); CP_COMMIT();
    stageW(0); CP_COMMIT();

    for (int tap = 0; tap < 25; ++tap) {
        const int dx = tap % 5;
        __syncthreads();                       // prior MMAs done (A + W bufs free)
        if (dx == 0 && tap > 0) { stageA(tap/5); CP_COMMIT(); }
        if (tap < 24) stageW(tap + 1);
        CP_COMMIT();
        CP_WAIT1();                            // everything but newest group done
        __syncthreads();

        const uint32_t wbuf = sb + ((tap & 1) ? O_W1 : O_W0);
        const int p0 = wid*32 + dx;
        #pragma unroll
        for (int k = 0; k < 4; ++k) {
            uint32_t ah[2][4], al[2][4];
            #pragma unroll
            for (int mt = 0; mt < 2; ++mt) {
                const uint32_t abyte = (uint32_t)((p0 + mt*16 + ar)*128 + k*32 + ak);
                LDSM_X4(ah[mt][0],ah[mt][1],ah[mt][2],ah[mt][3],
                        sb + O_AH + SWZ(abyte));
                LDSM_X4(al[mt][0],al[mt][1],al[mt][2],al[mt][3],
                        sb + O_AL + SWZ(abyte));
            }
            const uint32_t bbyte0 = (uint32_t)((k*16 + brow)*128);
            #pragma unroll
            for (int np = 0; np < 4; ++np) {
                const uint32_t bbyte = SWZ(bbyte0 + (np*2 + bnn)*16);
                uint32_t bh0,bh1,bh2,bh3, bl0,bl1,bl2,bl3;
                LDSM_X4T(bh0,bh1,bh2,bh3, wbuf + bbyte);
                LDSM_X4T(bl0,bl1,bl2,bl3, wbuf + 8192 + bbyte);
                #pragma unroll
                for (int mt = 0; mt < 2; ++mt) {
                    MMA_BF16(acc[mt][np*2],
                             ah[mt][0],ah[mt][1],ah[mt][2],ah[mt][3], bh0,bh1);
                    MMA_BF16(acc[mt][np*2],
                             ah[mt][0],ah[mt][1],ah[mt][2],ah[mt][3], bl0,bl1);
                    MMA_BF16(acc[mt][np*2],
                             al[mt][0],al[mt][1],al[mt][2],al[mt][3], bh0,bh1);
                    MMA_BF16(acc[mt][np*2+1],
                             ah[mt][0],ah[mt][1],ah[mt][2],ah[mt][3], bh2,bh3);
                    MMA_BF16(acc[mt][np*2+1],
                             ah[mt][0],ah[mt][1],ah[mt][2],ah[mt][3], bl2,bl3);
                    MMA_BF16(acc[mt][np*2+1],
                             al[mt][0],al[mt][1],al[mt][2],al[mt][3], bh2,bh3);
                }
            }
        }
    }

    // epilogue: BN + ReLU; write act (hi/lo) + pp += (f32)
    const int r0 = lane >> 2;
    const size_t rowoff = ((size_t)b*H + y)*W;
    #pragma unroll
    for (int mt = 0; mt < 2; ++mt) {
        const int gxa = x0 + wid*32 + mt*16 + r0;
        const int gxb = gxa + 8;
        #pragma unroll
        for (int nt = 0; nt < 8; ++nt) {
            const int co = nt*8 + (lane & 3)*2;
            const float s0 = scp[co], s1 = scp[co+1];
            const float c0 = bsp[co], c1 = bsp[co+1];
            #pragma unroll
            for (int half = 0; half < 2; ++half) {
                const int gx = half ? gxb : gxa;
                if (gx < W) {
                    const float va = fmaxf(fmaf(acc[mt][nt][half*2+0], s0, c0), 0.f);
                    const float vb = fmaxf(fmaf(acc[mt][nt][half*2+1], s1, c1), 0.f);
                    const uint32_t hp = packbf(va, vb);
                    const float la = va - __uint_as_float(hp << 16);
                    const float lb = vb - __uint_as_float(hp & 0xFFFF0000u);
                    const uint32_t lp = packbf(la, lb);
                    char* ab = yact + (rowoff + gx)*256 + co*2;
                    *(uint32_t*)ab         = hp;
                    *(uint32_t*)(ab + 128) = lp;
                    const size_t off = (rowoff + gx)*64 + co;
                    float2 p = *(float2*)(pp + off);
                    p.x += va; p.y += vb;
                    *(float2*)(pp + off) = p;
                }
            }
        }
    }
}

// ---------------------------------------------------------------------------
// conv 5x5, Cin=1 -> Cout=64, +bias, ReLU; writes act (hi/lo) and pp (f32)
// ---------------------------------------------------------------------------
__global__ void __launch_bounds__(256) conv_first(
    const float* __restrict__ x, const float* __restrict__ w,
    const float* __restrict__ bias,
    char* __restrict__ yact, float* __restrict__ pp, int H, int W)
{
    __shared__ float xs[12*12];
    __shared__ float ws[25*64];
    const int t = threadIdx.x;
    const int b = blockIdx.z;
    const int x0 = blockIdx.x*8 - 2, y0 = blockIdx.y*8 - 2;
    const float* xb = x + (size_t)b*H*W;
    if (t < 144) {
        int yy = y0 + t/12, xx = x0 + t%12;
        xs[t] = ((unsigned)yy < (unsigned)H && (unsigned)xx < (unsigned)W)
                ? xb[(size_t)yy*W + xx] : 0.f;
    }
    for (int i = t; i < 1600; i += 256) ws[i] = w[i];
    __syncthreads();

    const int cg = t & 15, pg = t >> 4;
    const int co0 = cg*4;
    int py[4], px[4];
    #pragma unroll
    for (int k = 0; k < 4; ++k) { int p = pg + 16*k; py[k] = p >> 3; px[k] = p & 7; }
    float acc[4][4];
    #pragma unroll
    for (int k = 0; k < 4; ++k)
        #pragma unroll
        for (int j = 0; j < 4; ++j) acc[k][j] = 0.f;

    #pragma unroll
    for (int tap = 0; tap < 25; ++tap) {
        const int dy = tap/5, dx = tap - 5*(tap/5);
        const float4 wv = *(const float4*)(ws + tap*64 + co0);
        #pragma unroll
        for (int k = 0; k < 4; ++k) {
            float a = xs[(py[k]+dy)*12 + px[k]+dx];
            acc[k][0] = fmaf(a, wv.x, acc[k][0]);
            acc[k][1] = fmaf(a, wv.y, acc[k][1]);
            acc[k][2] = fmaf(a, wv.z, acc[k][2]);
            acc[k][3] = fmaf(a, wv.w, acc[k][3]);
        }
    }
    const int gx0 = blockIdx.x*8, gy0 = blockIdx.y*8;
    float bs[4];
    #pragma unroll
    for (int j = 0; j < 4; ++j) bs[j] = bias[co0+j];
    #pragma unroll
    for (int k = 0; k < 4; ++k) {
        int gy = gy0 + py[k], gx = gx0 + px[k];
        if (gy < H && gx < W) {
            float r0 = fmaxf(acc[k][0] + bs[0], 0.f);
            float r1 = fmaxf(acc[k][1] + bs[1], 0.f);
            float r2 = fmaxf(acc[k][2] + bs[2], 0.f);
            float r3 = fmaxf(acc[k][3] + bs[3], 0.f);
            const size_t pix = ((size_t)b*H + gy)*W + gx;
            uint32_t h01 = packbf(r0, r1), h23 = packbf(r2, r3);
            float l0 = r0 - __uint_as_float(h01 << 16);
            float l1 = r1 - __uint_as_float(h01 & 0xFFFF0000u);
            float l2 = r2 - __uint_as_float(h23 << 16);
            float l3 = r3 - __uint_as_float(h23 & 0xFFFF0000u);
            uint32_t lo01 = packbf(l0, l1), lo23 = packbf(l2, l3);
            char* ab = yact + pix*256 + co0*2;
            *(uint2*)ab         = make_uint2(h01, h23);
            *(uint2*)(ab + 128) = make_uint2(lo01, lo23);
            *(float4*)(pp + pix*64 + co0) = make_float4(r0, r1, r2, r3);
        }
    }
}

// ---------------------------------------------------------------------------
// conv 5x5 64->1 in two channel-halves: out = conv(pp)*invM + bias + res
// smem per pass: xs 20*20*32 (51200B) + ws 25*32 (3200B) = 54400B -> 4 CTAs/SM
// ---------------------------------------------------------------------------
__global__ void __launch_bounds__(256) conv_last(
    const float* __restrict__ ppin, const float* __restrict__ w,
    const float* __restrict__ bias, const float* __restrict__ res,
    float* __restrict__ out, int H, int W, float invM)
{
    extern __shared__ float smemf[];
    float* xs = smemf;             // 20*20*32 = 12800 floats
    float* ws = smemf + 12800;     // 25*32 = 800 floats
    const int t = threadIdx.x;
    const int b = blockIdx.z;
    const int x0 = blockIdx.x*16 - 2, y0 = blockIdx.y*16 - 2;
    const float* xb = ppin + (size_t)b*H*W*64;

    const int ty = t >> 4, tx = t & 15;
    const int gy = blockIdx.y*16 + ty, gx = blockIdx.x*16 + tx;
    float acc = 0.f;

    for (int h = 0; h < 2; ++h) {
        __syncthreads();
        float4* xs4 = (float4*)xs;
        for (int i = t; i < 20*20*8; i += 256) {
            int p = i >> 3, c4 = i & 7;
            int yy = y0 + p/20, xx = x0 + p - 20*(p/20);
            float4 v = make_float4(0.f,0.f,0.f,0.f);
            if ((unsigned)yy < (unsigned)H && (unsigned)xx < (unsigned)W)
                v = *(const float4*)(xb + ((size_t)yy*W + xx)*64 + h*32 + c4*4);
            xs4[i] = v;
        }
        for (int i = t; i < 800; i += 256) {
            int tap = i >> 5, c = i & 31;
            ws[i] = w[tap*64 + h*32 + c];
        }
        __syncthreads();
        if (gy < H && gx < W) {
            for (int tap = 0; tap < 25; ++tap) {
                const int dy = tap/5, dx = tap - 5*(tap/5);
                const float4* xv = (const float4*)(xs + ((ty+dy)*20 + tx+dx)*32);
                const float4* wv = (const float4*)(ws + tap*32);
                #pragma unroll
                for (int c4 = 0; c4 < 8; ++c4) {
                    float4 a = xv[c4], q = wv[c4];
                    acc = fmaf(a.x, q.x, acc);
                    acc = fmaf(a.y, q.y, acc);
                    acc = fmaf(a.z, q.z, acc);
                    acc = fmaf(a.w, q.w, acc);
                }
            }
        }
    }
    if (gy < H && gx < W) {
        size_t pix = ((size_t)b*H + gy)*W + gx;
        out[pix] = fmaf(acc, invM, bias[0]) + res[pix];
    }
}

// ---------------------------------------------------------------------------
__global__ void __launch_bounds__(736) filter_kernel(
    const float* __restrict__ de_sin, const float* __restrict__ wb,
    float* __restrict__ filtT)
{
    __shared__ float xs[S_DET + S_DET - 1];
    __shared__ float wbs[S_DET];
    const int t = threadIdx.x;
    const int blk = blockIdx.x;
    const int b = blk / S_ANG, ang = blk - b*S_ANG;
    for (int i = t; i < 2*S_DET-1; i += 736) xs[i] = 0.f;
    if (t < S_DET) wbs[t] = wb[t];
    __syncthreads();
    if (t < S_DET)
        xs[362 + t] = de_sin[((size_t)b*S_DET + t)*S_ANG + ang];
    __syncthreads();
    if (t < S_DET) {
        float acc = 0.f;
        #pragma unroll 5
        for (int k = 0; k < S_DET; ++k)
            acc = fmaf(wbs[k], xs[t + k], acc);
        filtT[((size_t)ang*S_DET + t)*4 + b] = acc;
    }
}

// ---------------------------------------------------------------------------
__global__ void __launch_bounds__(256) backproj(
    const float* __restrict__ vals, const int* __restrict__ rows,
    const int* __restrict__ cols, const float4* __restrict__ filtT,
    float* __restrict__ fbpT)
{
    const long long s = ((long long)blockIdx.x*blockDim.x + threadIdx.x) * 16;
    if (s >= NNZ) return;
    int cur = rows[s];
    float a0 = 0.f, a1 = 0.f, a2 = 0.f, a3 = 0.f;
    #pragma unroll 4
    for (int j = 0; j < 16; ++j) {
        const long long i = s + j;
        const int r = rows[i];
        if (r != cur) {
            atomicAdd(&fbpT[(size_t)cur*4+0], a0);
            atomicAdd(&fbpT[(size_t)cur*4+1], a1);
            atomicAdd(&fbpT[(size_t)cur*4+2], a2);
            atomicAdd(&fbpT[(size_t)cur*4+3], a3);
            cur = r; a0 = a1 = a2 = a3 = 0.f;
        }
        const float v = vals[i];
        const float4 f = filtT[cols[i]];
        a0 = fmaf(v, f.x, a0);
        a1 = fmaf(v, f.y, a1);
        a2 = fmaf(v, f.z, a2);
        a3 = fmaf(v, f.w, a3);
    }
    atomicAdd(&fbpT[(size_t)cur*4+0], a0);
    atomicAdd(&fbpT[(size_t)cur*4+1], a1);
    atomicAdd(&fbpT[(size_t)cur*4+2], a2);
    atomicAdd(&fbpT[(size_t)cur*4+3], a3);
}

__global__ void __launch_bounds__(256) fbp_fin(
    const float* __restrict__ fbpT, float* __restrict__ fbp,
    float* __restrict__ out_fbp)
{
    const int i = blockIdx.x*blockDim.x + threadIdx.x;
    if (i >= IMG*IMG) return;
    const float4 v = *(const float4*)(fbpT + (size_t)i*4);
    const float r0 = 4.f*v.x, r1 = 4.f*v.y, r2 = 4.f*v.z, r3 = 4.f*v.w;
    fbp[0*IMG*IMG + i] = r0;  out_fbp[0*IMG*IMG + i] = r0;
    fbp[1*IMG*IMG + i] = r1;  out_fbp[1*IMG*IMG + i] = r1;
    fbp[2*IMG*IMG + i] = r2;  out_fbp[2*IMG*IMG + i] = r2;
    fbp[3*IMG*IMG + i] = r3;  out_fbp[3*IMG*IMG + i] = r3;
}

// ---------------------------------------------------------------------------
extern "C" void kernel_launch(void* const* d_in, const int* in_sizes, int n_in,
                              void* d_out, int out_size)
{
    const float* inputs    = (const float*)d_in[0];
    const float* w_sin1    = (const float*)d_in[1];
    const float* b_sin1    = (const float*)d_in[2];
    const float* w_sin_mid = (const float*)d_in[3];
    const float* sin_gamma = (const float*)d_in[4];
    const float* sin_beta  = (const float*)d_in[5];
    const float* sin_mean  = (const float*)d_in[6];
    const float* sin_var   = (const float*)d_in[7];
    const float* w_sin6    = (const float*)d_in[8];
    const float* b_sin6    = (const float*)d_in[9];
    const float* w_ct1     = (const float*)d_in[10];
    const float* b_ct1     = (const float*)d_in[11];
    const float* w_ct_mid  = (const float*)d_in[12];
    const float* ct_gamma  = (const float*)d_in[13];
    const float* ct_beta   = (const float*)d_in[14];
    const float* ct_mean   = (const float*)d_in[15];
    const float* ct_var    = (const float*)d_in[16];
    const float* w_ct6     = (const float*)d_in[17];
    const float* b_ct6     = (const float*)d_in[18];
    const float* w_b       = (const float*)d_in[19];
    const float* at_vals   = (const float*)d_in[20];
    const int*   at_rows   = (const int*)d_in[21];
    const int*   at_cols   = (const int*)d_in[22];

    float *pA, *pB, *pC, *pFiltT, *pFbpT, *pFbp;
    char* pW;
    cudaGetSymbolAddress((void**)&pA, g_A);
    cudaGetSymbolAddress((void**)&pB, g_B);
    cudaGetSymbolAddress((void**)&pC, g_C);
    cudaGetSymbolAddress((void**)&pW, g_W);
    cudaGetSymbolAddress((void**)&pFiltT, g_filtT);
    cudaGetSymbolAddress((void**)&pFbpT, g_fbpT);
    cudaGetSymbolAddress((void**)&pFbp, g_fbp);

    cudaFuncSetAttribute(conv_mid_mma, cudaFuncAttributeMaxDynamicSharedMemorySize, MMSM);
    cudaFuncSetAttribute(conv_last,    cudaFuncAttributeMaxDynamicSharedMemorySize, 54400);

    float* out_desin = (float*)d_out;
    float* out_img   = out_desin + 4*S_DET*S_ANG;
    float* out_fbp   = out_img + 4*IMG*IMG;

    char* actA = (char*)pA;
    char* actC = (char*)pC;

    // --- sinogram CNN ---
    {
        prep_w<<<(4*25*4096 + 255)/256, 256>>>(w_sin_mid, pW, 4);
        dim3 gs((S_ANG+7)/8, (S_DET+7)/8, NB);
        conv_first<<<gs, 256>>>(inputs, w_sin1, b_sin1, actA, pB, S_DET, S_ANG);
        dim3 gm((S_ANG+127)/128, S_DET, NB);
        char* cur = actA; char* nxt = actC;
        for (int i = 0; i < 4; ++i) {
            conv_mid_mma<<<gm, 128, MMSM>>>(cur, pW + (size_t)i*409600,
                                            sin_gamma + i*64, sin_beta + i*64,
                                            sin_mean + i*64, sin_var + i*64,
                                            nxt, pB, S_DET, S_ANG);
            char* tmp = cur; cur = nxt; nxt = tmp;
        }
        dim3 gs2((S_ANG+15)/16, (S_DET+15)/16, NB);
        conv_last<<<gs2, 256, 54400>>>(pB, w_sin6, b_sin6, inputs, out_desin,
                                       S_DET, S_ANG, 0.25f);
    }

    // --- FBP decode ---
    filter_kernel<<<NB*S_ANG, 736>>>(out_desin, w_b, pFiltT);
    cudaMemsetAsync(pFbpT, 0, (size_t)IMG*IMG*4*sizeof(float));
    backproj<<<(int)(NNZ/16/256), 256>>>(at_vals, at_rows, at_cols,
                                         (const float4*)pFiltT, pFbpT);
    fbp_fin<<<(IMG*IMG+255)/256, 256>>>(pFbpT, pFbp, out_fbp);

    // --- image CNN ---
    {
        prep_w<<<(5*25*4096 + 255)/256, 256>>>(w_ct_mid, pW, 5);
        dim3 gi(IMG/8, IMG/8, NB);
        conv_first<<<gi, 256>>>(pFbp, w_ct1, b_ct1, actA, pB, IMG, IMG);
        dim3 gm(IMG/128, IMG, NB);
        char* cur = actA; char* nxt = actC;
        for (int i = 0; i < 5; ++i) {
            conv_mid_mma<<<gm, 128, MMSM>>>(cur, pW + (size_t)i*409600,
                                            ct_gamma + i*64, ct_beta + i*64,
                                            ct_mean + i*64, ct_var + i*64,
                                            nxt, pB, IMG, IMG);
            char* tmp = cur; cur = nxt; nxt = tmp;
        }
        dim3 gi2(IMG/16, IMG/16, NB);
        conv_last<<<gi2, 256, 54400>>>(pB, w_ct6, b_ct6, pFbp, out_img,
                                       IMG, IMG, 0.2f);
    }
}

// round 13
// speedup vs baseline: 1.0837x; 1.0039x over previous
#include <cuda_runtime.h>
#include <cuda_bf16.h>
#include <cstdint>
#include <cstddef>

#define S_DET 725
#define S_ANG 360
#define IMG   512
#define NNZ   8388608LL
#define NB    4

#define ACTN (4ULL*512*512*64)
__device__ float g_A[ACTN];                 // act ping (256B/px hi/lo records)
__device__ float g_B[ACTN];                 // pp accumulator (f32)
__device__ float g_C[ACTN];                 // act pong
__device__ char  g_W[9*25*16384];           // pre-converted weights (swizzled hi/lo)
__device__ float g_filtT[S_DET*S_ANG*4];
__device__ float g_fbpT[IMG*IMG*4];
__device__ float g_fbp[4*IMG*IMG];

__device__ __forceinline__ uint32_t smem_u32(const void* p) {
    uint32_t a;
    asm("{ .reg .u64 t; cvta.to.shared.u64 t, %1; cvt.u32.u64 %0, t; }"
        : "=r"(a) : "l"(p));
    return a;
}
__device__ __forceinline__ uint32_t packbf(float lo, float hi) {
    uint32_t r;
    asm("cvt.rn.bf16x2.f32 %0, %1, %2;" : "=r"(r) : "f"(hi), "f"(lo));
    return r;
}
#define SWZ(o) ((o) ^ (((o) >> 3) & 0x70))

#define CP_ASYNC16(dst_u32, src) \
    asm volatile("cp.async.cg.shared.global [%0], [%1], 16;" :: "r"(dst_u32), "l"(src))
#define CP_COMMIT() asm volatile("cp.async.commit_group;")
#define CP_WAIT0()  asm volatile("cp.async.wait_group 0;")

#define LDSM_X4(r0,r1,r2,r3,addr) \
    asm volatile("ldmatrix.sync.aligned.m8n8.x4.shared.b16 {%0,%1,%2,%3}, [%4];" \
        : "=r"(r0),"=r"(r1),"=r"(r2),"=r"(r3) : "r"(addr))
#define LDSM_X4T(r0,r1,r2,r3,addr) \
    asm volatile("ldmatrix.sync.aligned.m8n8.x4.trans.shared.b16 {%0,%1,%2,%3}, [%4];" \
        : "=r"(r0),"=r"(r1),"=r"(r2),"=r"(r3) : "r"(addr))
#define MMA_BF16(d,a0,a1,a2,a3,b0,b1) \
    asm volatile("mma.sync.aligned.m16n8k16.row.col.f32.bf16.bf16.f32 " \
        "{%0,%1,%2,%3}, {%4,%5,%6,%7}, {%8,%9}, {%0,%1,%2,%3};" \
        : "+f"((d)[0]),"+f"((d)[1]),"+f"((d)[2]),"+f"((d)[3]) \
        : "r"(a0),"r"(a1),"r"(a2),"r"(a3),"r"(b0),"r"(b1))

// smem map (1024-aligned swizzle regions) — single W buffer, 4 CTAs/SM
#define O_BN  0
#define O_AH  1024                 // 132*128 = 16896
#define O_AL  18432                // 16896
#define O_W   35840                // 16384 (hi 8192 | lo 8192)
#define MMSM  52224

// ---------------------------------------------------------------------------
// prep: convert conv weights f32 -> bf16 hi/lo, swizzled panel layout
// ---------------------------------------------------------------------------
__global__ void __launch_bounds__(256) prep_w(
    const float* __restrict__ w, char* __restrict__ gw, int layers)
{
    const int idx = blockIdx.x*blockDim.x + threadIdx.x;
    if (idx >= layers*25*4096) return;
    const int l = idx / 102400, r = idx - l*102400;
    const int tap = r >> 12, e = r & 4095;
    const int ci = e >> 6, co = e & 63;
    const float f = w[(size_t)l*102400 + tap*4096 + ci*64 + co];
    const uint32_t hb = packbf(f, 0.f) & 0xFFFFu;
    const float lf = f - __uint_as_float(hb << 16);
    const uint32_t lb = packbf(lf, 0.f) & 0xFFFFu;
    char* base = gw + (size_t)l*409600 + tap*16384;
    const uint32_t off = SWZ((uint32_t)(ci*128 + co*2));
    *(uint16_t*)(base + off)        = (uint16_t)hb;
    *(uint16_t*)(base + 8192 + off) = (uint16_t)lb;
}

// ---------------------------------------------------------------------------
// conv 5x5 64->64 + BN + ReLU via mma.sync bf16 split; single-W-buffer,
// 4 CTAs/SM (inter-CTA latency hiding). act records 256B/px [hi|lo].
// pp += result (f32). CTA: 128 px of row y. 128 threads, 4 warps.
// ---------------------------------------------------------------------------
__global__ void __launch_bounds__(128, 4) conv_mid_mma(
    const char* __restrict__ xact, const char* __restrict__ wconv,
    const float* __restrict__ gamma, const float* __restrict__ beta,
    const float* __restrict__ mean, const float* __restrict__ var,
    char* __restrict__ yact, float* __restrict__ pp, int H, int W)
{
    extern __shared__ char sm[];
    const uint32_t sb = smem_u32(sm);
    const int t = threadIdx.x, lane = t & 31, wid = t >> 5;
    const int b = blockIdx.z, y = blockIdx.y, x0 = blockIdx.x*128;

    float* scp = (float*)(sm + O_BN);
    float* bsp = scp + 64;
    if (t < 64) {
        float s = gamma[t] * rsqrtf(var[t] + 1e-3f);
        scp[t] = s; bsp[t] = beta[t] - mean[t]*s;
    }

    float acc[2][8][4];
    #pragma unroll
    for (int mt = 0; mt < 2; ++mt)
        #pragma unroll
        for (int n = 0; n < 8; ++n)
            acc[mt][n][0] = acc[mt][n][1] = acc[mt][n][2] = acc[mt][n][3] = 0.f;

    const int ar = lane & 15;
    const int ak = (lane >> 4) * 16;
    const int brow = ((lane >> 3) & 1)*8 + (lane & 7);
    const int bnn  = (lane >> 4);

    auto stageA = [&](int dy) {
        const int yin = y - 2 + dy;
        const bool yok = (unsigned)yin < (unsigned)H;
        const char* xr = xact + ((size_t)b*H + (yok ? yin : 0))*W*256;
        for (int i = t; i < 2112; i += 128) {
            const int p = i >> 4, j = i & 15;
            const int xin = x0 + p - 2;
            const uint32_t rel = (j < 8 ? O_AH : O_AL)
                               + SWZ((uint32_t)(p*128 + (j & 7)*16));
            if (yok && (unsigned)xin < (unsigned)W) {
                CP_ASYNC16(sb + rel,
                           xr + (size_t)xin*256 + (j < 8 ? j*16 : 128 + (j-8)*16));
            } else {
                *(uint4*)(sm + rel) = make_uint4(0,0,0,0);
            }
        }
    };
    auto stageW = [&](int tap) {
        const char* src = wconv + (size_t)tap*16384;
        #pragma unroll
        for (int j = 0; j < 8; ++j)
            CP_ASYNC16(sb + O_W + (t + j*128)*16, src + (t + j*128)*16);
    };

    for (int tap = 0; tap < 25; ++tap) {
        const int dx = tap % 5, dy = tap / 5;
        __syncthreads();                 // prior MMAs done; A/W buffers reusable
        if (dx == 0) stageA(dy);
        stageW(tap);
        CP_COMMIT();
        CP_WAIT0();
        __syncthreads();

        const int p0 = wid*32 + dx;
        #pragma unroll
        for (int k = 0; k < 4; ++k) {
            uint32_t ah[2][4], al[2][4];
            #pragma unroll
            for (int mt = 0; mt < 2; ++mt) {
                const uint32_t abyte = (uint32_t)((p0 + mt*16 + ar)*128 + k*32 + ak);
                LDSM_X4(ah[mt][0],ah[mt][1],ah[mt][2],ah[mt][3],
                        sb + O_AH + SWZ(abyte));
                LDSM_X4(al[mt][0],al[mt][1],al[mt][2],al[mt][3],
                        sb + O_AL + SWZ(abyte));
            }
            const uint32_t bbyte0 = (uint32_t)((k*16 + brow)*128);
            #pragma unroll
            for (int np = 0; np < 4; ++np) {
                const uint32_t bbyte = SWZ(bbyte0 + (np*2 + bnn)*16);
                uint32_t bh0,bh1,bh2,bh3, bl0,bl1,bl2,bl3;
                LDSM_X4T(bh0,bh1,bh2,bh3, sb + O_W + bbyte);
                LDSM_X4T(bl0,bl1,bl2,bl3, sb + O_W + 8192 + bbyte);
                #pragma unroll
                for (int mt = 0; mt < 2; ++mt) {
                    MMA_BF16(acc[mt][np*2],
                             ah[mt][0],ah[mt][1],ah[mt][2],ah[mt][3], bh0,bh1);
                    MMA_BF16(acc[mt][np*2],
                             ah[mt][0],ah[mt][1],ah[mt][2],ah[mt][3], bl0,bl1);
                    MMA_BF16(acc[mt][np*2],
                             al[mt][0],al[mt][1],al[mt][2],al[mt][3], bh0,bh1);
                    MMA_BF16(acc[mt][np*2+1],
                             ah[mt][0],ah[mt][1],ah[mt][2],ah[mt][3], bh2,bh3);
                    MMA_BF16(acc[mt][np*2+1],
                             ah[mt][0],ah[mt][1],ah[mt][2],ah[mt][3], bl2,bl3);
                    MMA_BF16(acc[mt][np*2+1],
                             al[mt][0],al[mt][1],al[mt][2],al[mt][3], bh2,bh3);
                }
            }
        }
    }

    // epilogue: BN + ReLU; write act (hi/lo) + pp += (f32)
    const int r0 = lane >> 2;
    const size_t rowoff = ((size_t)b*H + y)*W;
    #pragma unroll
    for (int mt = 0; mt < 2; ++mt) {
        const int gxa = x0 + wid*32 + mt*16 + r0;
        const int gxb = gxa + 8;
        #pragma unroll
        for (int nt = 0; nt < 8; ++nt) {
            const int co = nt*8 + (lane & 3)*2;
            const float s0 = scp[co], s1 = scp[co+1];
            const float c0 = bsp[co], c1 = bsp[co+1];
            #pragma unroll
            for (int half = 0; half < 2; ++half) {
                const int gx = half ? gxb : gxa;
                if (gx < W) {
                    const float va = fmaxf(fmaf(acc[mt][nt][half*2+0], s0, c0), 0.f);
                    const float vb = fmaxf(fmaf(acc[mt][nt][half*2+1], s1, c1), 0.f);
                    const uint32_t hp = packbf(va, vb);
                    const float la = va - __uint_as_float(hp << 16);
                    const float lb = vb - __uint_as_float(hp & 0xFFFF0000u);
                    const uint32_t lp = packbf(la, lb);
                    char* ab = yact + (rowoff + gx)*256 + co*2;
                    *(uint32_t*)ab         = hp;
                    *(uint32_t*)(ab + 128) = lp;
                    const size_t off = (rowoff + gx)*64 + co;
                    float2 p = *(float2*)(pp + off);
                    p.x += va; p.y += vb;
                    *(float2*)(pp + off) = p;
                }
            }
        }
    }
}

// ---------------------------------------------------------------------------
// conv 5x5, Cin=1 -> Cout=64, +bias, ReLU; writes act (hi/lo) and pp (f32)
// ---------------------------------------------------------------------------
__global__ void __launch_bounds__(256) conv_first(
    const float* __restrict__ x, const float* __restrict__ w,
    const float* __restrict__ bias,
    char* __restrict__ yact, float* __restrict__ pp, int H, int W)
{
    __shared__ float xs[12*12];
    __shared__ float ws[25*64];
    const int t = threadIdx.x;
    const int b = blockIdx.z;
    const int x0 = blockIdx.x*8 - 2, y0 = blockIdx.y*8 - 2;
    const float* xb = x + (size_t)b*H*W;
    if (t < 144) {
        int yy = y0 + t/12, xx = x0 + t%12;
        xs[t] = ((unsigned)yy < (unsigned)H && (unsigned)xx < (unsigned)W)
                ? xb[(size_t)yy*W + xx] : 0.f;
    }
    for (int i = t; i < 1600; i += 256) ws[i] = w[i];
    __syncthreads();

    const int cg = t & 15, pg = t >> 4;
    const int co0 = cg*4;
    int py[4], px[4];
    #pragma unroll
    for (int k = 0; k < 4; ++k) { int p = pg + 16*k; py[k] = p >> 3; px[k] = p & 7; }
    float acc[4][4];
    #pragma unroll
    for (int k = 0; k < 4; ++k)
        #pragma unroll
        for (int j = 0; j < 4; ++j) acc[k][j] = 0.f;

    #pragma unroll
    for (int tap = 0; tap < 25; ++tap) {
        const int dy = tap/5, dx = tap - 5*(tap/5);
        const float4 wv = *(const float4*)(ws + tap*64 + co0);
        #pragma unroll
        for (int k = 0; k < 4; ++k) {
            float a = xs[(py[k]+dy)*12 + px[k]+dx];
            acc[k][0] = fmaf(a, wv.x, acc[k][0]);
            acc[k][1] = fmaf(a, wv.y, acc[k][1]);
            acc[k][2] = fmaf(a, wv.z, acc[k][2]);
            acc[k][3] = fmaf(a, wv.w, acc[k][3]);
        }
    }
    const int gx0 = blockIdx.x*8, gy0 = blockIdx.y*8;
    float bs[4];
    #pragma unroll
    for (int j = 0; j < 4; ++j) bs[j] = bias[co0+j];
    #pragma unroll
    for (int k = 0; k < 4; ++k) {
        int gy = gy0 + py[k], gx = gx0 + px[k];
        if (gy < H && gx < W) {
            float r0 = fmaxf(acc[k][0] + bs[0], 0.f);
            float r1 = fmaxf(acc[k][1] + bs[1], 0.f);
            float r2 = fmaxf(acc[k][2] + bs[2], 0.f);
            float r3 = fmaxf(acc[k][3] + bs[3], 0.f);
            const size_t pix = ((size_t)b*H + gy)*W + gx;
            uint32_t h01 = packbf(r0, r1), h23 = packbf(r2, r3);
            float l0 = r0 - __uint_as_float(h01 << 16);
            float l1 = r1 - __uint_as_float(h01 & 0xFFFF0000u);
            float l2 = r2 - __uint_as_float(h23 << 16);
            float l3 = r3 - __uint_as_float(h23 & 0xFFFF0000u);
            uint32_t lo01 = packbf(l0, l1), lo23 = packbf(l2, l3);
            char* ab = yact + pix*256 + co0*2;
            *(uint2*)ab         = make_uint2(h01, h23);
            *(uint2*)(ab + 128) = make_uint2(lo01, lo23);
            *(float4*)(pp + pix*64 + co0) = make_float4(r0, r1, r2, r3);
        }
    }
}

// ---------------------------------------------------------------------------
// conv 5x5 64->1 in two channel-halves: out = conv(pp)*invM + bias + res
// ---------------------------------------------------------------------------
__global__ void __launch_bounds__(256) conv_last(
    const float* __restrict__ ppin, const float* __restrict__ w,
    const float* __restrict__ bias, const float* __restrict__ res,
    float* __restrict__ out, int H, int W, float invM)
{
    extern __shared__ float smemf[];
    float* xs = smemf;             // 20*20*32 = 12800 floats
    float* ws = smemf + 12800;     // 25*32 = 800 floats
    const int t = threadIdx.x;
    const int b = blockIdx.z;
    const int x0 = blockIdx.x*16 - 2, y0 = blockIdx.y*16 - 2;
    const float* xb = ppin + (size_t)b*H*W*64;

    const int ty = t >> 4, tx = t & 15;
    const int gy = blockIdx.y*16 + ty, gx = blockIdx.x*16 + tx;
    float acc = 0.f;

    for (int h = 0; h < 2; ++h) {
        __syncthreads();
        float4* xs4 = (float4*)xs;
        for (int i = t; i < 20*20*8; i += 256) {
            int p = i >> 3, c4 = i & 7;
            int yy = y0 + p/20, xx = x0 + p - 20*(p/20);
            float4 v = make_float4(0.f,0.f,0.f,0.f);
            if ((unsigned)yy < (unsigned)H && (unsigned)xx < (unsigned)W)
                v = *(const float4*)(xb + ((size_t)yy*W + xx)*64 + h*32 + c4*4);
            xs4[i] = v;
        }
        for (int i = t; i < 800; i += 256) {
            int tap = i >> 5, c = i & 31;
            ws[i] = w[tap*64 + h*32 + c];
        }
        __syncthreads();
        if (gy < H && gx < W) {
            for (int tap = 0; tap < 25; ++tap) {
                const int dy = tap/5, dx = tap - 5*(tap/5);
                const float4* xv = (const float4*)(xs + ((ty+dy)*20 + tx+dx)*32);
                const float4* wv = (const float4*)(ws + tap*32);
                #pragma unroll
                for (int c4 = 0; c4 < 8; ++c4) {
                    float4 a = xv[c4], q = wv[c4];
                    acc = fmaf(a.x, q.x, acc);
                    acc = fmaf(a.y, q.y, acc);
                    acc = fmaf(a.z, q.z, acc);
                    acc = fmaf(a.w, q.w, acc);
                }
            }
        }
    }
    if (gy < H && gx < W) {
        size_t pix = ((size_t)b*H + gy)*W + gx;
        out[pix] = fmaf(acc, invM, bias[0]) + res[pix];
    }
}

// ---------------------------------------------------------------------------
__global__ void __launch_bounds__(736) filter_kernel(
    const float* __restrict__ de_sin, const float* __restrict__ wb,
    float* __restrict__ filtT)
{
    __shared__ float xs[S_DET + S_DET - 1];
    __shared__ float wbs[S_DET];
    const int t = threadIdx.x;
    const int blk = blockIdx.x;
    const int b = blk / S_ANG, ang = blk - b*S_ANG;
    for (int i = t; i < 2*S_DET-1; i += 736) xs[i] = 0.f;
    if (t < S_DET) wbs[t] = wb[t];
    __syncthreads();
    if (t < S_DET)
        xs[362 + t] = de_sin[((size_t)b*S_DET + t)*S_ANG + ang];
    __syncthreads();
    if (t < S_DET) {
        float acc = 0.f;
        #pragma unroll 5
        for (int k = 0; k < S_DET; ++k)
            acc = fmaf(wbs[k], xs[t + k], acc);
        filtT[((size_t)ang*S_DET + t)*4 + b] = acc;
    }
}

// ---------------------------------------------------------------------------
__global__ void __launch_bounds__(256) backproj(
    const float* __restrict__ vals, const int* __restrict__ rows,
    const int* __restrict__ cols, const float4* __restrict__ filtT,
    float* __restrict__ fbpT)
{
    const long long s = ((long long)blockIdx.x*blockDim.x + threadIdx.x) * 16;
    if (s >= NNZ) return;
    int cur = rows[s];
    float a0 = 0.f, a1 = 0.f, a2 = 0.f, a3 = 0.f;
    #pragma unroll 4
    for (int j = 0; j < 16; ++j) {
        const long long i = s + j;
        const int r = rows[i];
        if (r != cur) {
            atomicAdd(&fbpT[(size_t)cur*4+0], a0);
            atomicAdd(&fbpT[(size_t)cur*4+1], a1);
            atomicAdd(&fbpT[(size_t)cur*4+2], a2);
            atomicAdd(&fbpT[(size_t)cur*4+3], a3);
            cur = r; a0 = a1 = a2 = a3 = 0.f;
        }
        const float v = vals[i];
        const float4 f = filtT[cols[i]];
        a0 = fmaf(v, f.x, a0);
        a1 = fmaf(v, f.y, a1);
        a2 = fmaf(v, f.z, a2);
        a3 = fmaf(v, f.w, a3);
    }
    atomicAdd(&fbpT[(size_t)cur*4+0], a0);
    atomicAdd(&fbpT[(size_t)cur*4+1], a1);
    atomicAdd(&fbpT[(size_t)cur*4+2], a2);
    atomicAdd(&fbpT[(size_t)cur*4+3], a3);
}

__global__ void __launch_bounds__(256) fbp_fin(
    const float* __restrict__ fbpT, float* __restrict__ fbp,
    float* __restrict__ out_fbp)
{
    const int i = blockIdx.x*blockDim.x + threadIdx.x;
    if (i >= IMG*IMG) return;
    const float4 v = *(const float4*)(fbpT + (size_t)i*4);
    const float r0 = 4.f*v.x, r1 = 4.f*v.y, r2 = 4.f*v.z, r3 = 4.f*v.w;
    fbp[0*IMG*IMG + i] = r0;  out_fbp[0*IMG*IMG + i] = r0;
    fbp[1*IMG*IMG + i] = r1;  out_fbp[1*IMG*IMG + i] = r1;
    fbp[2*IMG*IMG + i] = r2;  out_fbp[2*IMG*IMG + i] = r2;
    fbp[3*IMG*IMG + i] = r3;  out_fbp[3*IMG*IMG + i] = r3;
}

// ---------------------------------------------------------------------------
extern "C" void kernel_launch(void* const* d_in, const int* in_sizes, int n_in,
                              void* d_out, int out_size)
{
    const float* inputs    = (const float*)d_in[0];
    const float* w_sin1    = (const float*)d_in[1];
    const float* b_sin1    = (const float*)d_in[2];
    const float* w_sin_mid = (const float*)d_in[3];
    const float* sin_gamma = (const float*)d_in[4];
    const float* sin_beta  = (const float*)d_in[5];
    const float* sin_mean  = (const float*)d_in[6];
    const float* sin_var   = (const float*)d_in[7];
    const float* w_sin6    = (const float*)d_in[8];
    const float* b_sin6    = (const float*)d_in[9];
    const float* w_ct1     = (const float*)d_in[10];
    const float* b_ct1     = (const float*)d_in[11];
    const float* w_ct_mid  = (const float*)d_in[12];
    const float* ct_gamma  = (const float*)d_in[13];
    const float* ct_beta   = (const float*)d_in[14];
    const float* ct_mean   = (const float*)d_in[15];
    const float* ct_var    = (const float*)d_in[16];
    const float* w_ct6     = (const float*)d_in[17];
    const float* b_ct6     = (const float*)d_in[18];
    const float* w_b       = (const float*)d_in[19];
    const float* at_vals   = (const float*)d_in[20];
    const int*   at_rows   = (const int*)d_in[21];
    const int*   at_cols   = (const int*)d_in[22];

    float *pA, *pB, *pC, *pFiltT, *pFbpT, *pFbp;
    char* pW;
    cudaGetSymbolAddress((void**)&pA, g_A);
    cudaGetSymbolAddress((void**)&pB, g_B);
    cudaGetSymbolAddress((void**)&pC, g_C);
    cudaGetSymbolAddress((void**)&pW, g_W);
    cudaGetSymbolAddress((void**)&pFiltT, g_filtT);
    cudaGetSymbolAddress((void**)&pFbpT, g_fbpT);
    cudaGetSymbolAddress((void**)&pFbp, g_fbp);

    cudaFuncSetAttribute(conv_mid_mma, cudaFuncAttributeMaxDynamicSharedMemorySize, MMSM);
    cudaFuncSetAttribute(conv_last,    cudaFuncAttributeMaxDynamicSharedMemorySize, 54400);

    float* out_desin = (float*)d_out;
    float* out_img   = out_desin + 4*S_DET*S_ANG;
    float* out_fbp   = out_img + 4*IMG*IMG;

    char* actA = (char*)pA;
    char* actC = (char*)pC;
    char* pWsin = pW;
    char* pWct  = pW + (size_t)4*409600;

    // convert all conv_mid weights up front (independent of everything else)
    prep_w<<<(4*25*4096 + 255)/256, 256>>>(w_sin_mid, pWsin, 4);
    prep_w<<<(5*25*4096 + 255)/256, 256>>>(w_ct_mid, pWct, 5);

    // --- sinogram CNN ---
    {
        dim3 gs((S_ANG+7)/8, (S_DET+7)/8, NB);
        conv_first<<<gs, 256>>>(inputs, w_sin1, b_sin1, actA, pB, S_DET, S_ANG);
        dim3 gm((S_ANG+127)/128, S_DET, NB);
        char* cur = actA; char* nxt = actC;
        for (int i = 0; i < 4; ++i) {
            conv_mid_mma<<<gm, 128, MMSM>>>(cur, pWsin + (size_t)i*409600,
                                            sin_gamma + i*64, sin_beta + i*64,
                                            sin_mean + i*64, sin_var + i*64,
                                            nxt, pB, S_DET, S_ANG);
            char* tmp = cur; cur = nxt; nxt = tmp;
        }
        dim3 gs2((S_ANG+15)/16, (S_DET+15)/16, NB);
        conv_last<<<gs2, 256, 54400>>>(pB, w_sin6, b_sin6, inputs, out_desin,
                                       S_DET, S_ANG, 0.25f);
    }

    // --- FBP decode ---
    filter_kernel<<<NB*S_ANG, 736>>>(out_desin, w_b, pFiltT);
    cudaMemsetAsync(pFbpT, 0, (size_t)IMG*IMG*4*sizeof(float));
    backproj<<<(int)(NNZ/16/256), 256>>>(at_vals, at_rows, at_cols,
                                         (const float4*)pFiltT, pFbpT);
    fbp_fin<<<(IMG*IMG+255)/256, 256>>>(pFbpT, pFbp, out_fbp);

    // --- image CNN ---
    {
        dim3 gi(IMG/8, IMG/8, NB);
        conv_first<<<gi, 256>>>(pFbp, w_ct1, b_ct1, actA, pB, IMG, IMG);
        dim3 gm(IMG/128, IMG, NB);
        char* cur = actA; char* nxt = actC;
        for (int i = 0; i < 5; ++i) {
            conv_mid_mma<<<gm, 128, MMSM>>>(cur, pWct + (size_t)i*409600,
                                            ct_gamma + i*64, ct_beta + i*64,
                                            ct_mean + i*64, ct_var + i*64,
                                            nxt, pB, IMG, IMG);
            char* tmp = cur; cur = nxt; nxt = tmp;
        }
        dim3 gi2(IMG/16, IMG/16, NB);
        conv_last<<<gi2, 256, 54400>>>(pB, w_ct6, b_ct6, pFbp, out_img,
                                       IMG, IMG, 0.2f);
    }
}

// round 15
// speedup vs baseline: 1.0896x; 1.0054x over previous
#include <cuda_runtime.h>
#include <cuda_bf16.h>
#include <cstdint>
#include <cstddef>

#define S_DET 725
#define S_ANG 360
#define IMG   512
#define NNZ   8388608LL
#define NB    4

#define ACTN (4ULL*512*512*64)
__device__ float g_A[ACTN];                 // act ping (256B/px hi/lo records)
__device__ float g_B[ACTN];                 // pp accumulator (f32)
__device__ float g_C[ACTN];                 // act pong
__device__ char  g_W[9*25*16384];           // pre-converted weights (swizzled hi/lo)
__device__ float g_filtT[S_DET*S_ANG*4];
__device__ float g_fbpT[IMG*IMG*4];
__device__ float g_fbp[4*IMG*IMG];

__device__ __forceinline__ uint32_t smem_u32(const void* p) {
    uint32_t a;
    asm("{ .reg .u64 t; cvta.to.shared.u64 t, %1; cvt.u32.u64 %0, t; }"
        : "=r"(a) : "l"(p));
    return a;
}
__device__ __forceinline__ uint32_t packbf(float lo, float hi) {
    uint32_t r;
    asm("cvt.rn.bf16x2.f32 %0, %1, %2;" : "=r"(r) : "f"(hi), "f"(lo));
    return r;
}
#define SWZ(o) ((o) ^ (((o) >> 3) & 0x70))

#define CP_ASYNC16(dst_u32, src) \
    asm volatile("cp.async.cg.shared.global [%0], [%1], 16;" :: "r"(dst_u32), "l"(src))
#define CP_COMMIT() asm volatile("cp.async.commit_group;")
#define CP_WAIT0()  asm volatile("cp.async.wait_group 0;")

#define LDSM_X4(r0,r1,r2,r3,addr) \
    asm volatile("ldmatrix.sync.aligned.m8n8.x4.shared.b16 {%0,%1,%2,%3}, [%4];" \
        : "=r"(r0),"=r"(r1),"=r"(r2),"=r"(r3) : "r"(addr))
#define LDSM_X4T(r0,r1,r2,r3,addr) \
    asm volatile("ldmatrix.sync.aligned.m8n8.x4.trans.shared.b16 {%0,%1,%2,%3}, [%4];" \
        : "=r"(r0),"=r"(r1),"=r"(r2),"=r"(r3) : "r"(addr))
#define MMA_BF16(d,a0,a1,a2,a3,b0,b1) \
    asm volatile("mma.sync.aligned.m16n8k16.row.col.f32.bf16.bf16.f32 " \
        "{%0,%1,%2,%3}, {%4,%5,%6,%7}, {%8,%9}, {%0,%1,%2,%3};" \
        : "+f"((d)[0]),"+f"((d)[1]),"+f"((d)[2]),"+f"((d)[3]) \
        : "r"(a0),"r"(a1),"r"(a2),"r"(a3),"r"(b0),"r"(b1))

// smem map (1024-aligned swizzle regions) — single W buffer, 4 CTAs/SM
#define O_BN  0
#define O_AH  1024                 // 132*128 = 16896
#define O_AL  18432                // 16896
#define O_W   35840                // 16384 (hi 8192 | lo 8192)
#define MMSM  52224

// ---------------------------------------------------------------------------
// prep: convert conv weights f32 -> bf16 hi/lo, swizzled panel layout
// ---------------------------------------------------------------------------
__global__ void __launch_bounds__(256) prep_w(
    const float* __restrict__ w, char* __restrict__ gw, int layers)
{
    const int idx = blockIdx.x*blockDim.x + threadIdx.x;
    if (idx >= layers*25*4096) return;
    const int l = idx / 102400, r = idx - l*102400;
    const int tap = r >> 12, e = r & 4095;
    const int ci = e >> 6, co = e & 63;
    const float f = w[(size_t)l*102400 + tap*4096 + ci*64 + co];
    const uint32_t hb = packbf(f, 0.f) & 0xFFFFu;
    const float lf = f - __uint_as_float(hb << 16);
    const uint32_t lb = packbf(lf, 0.f) & 0xFFFFu;
    char* base = gw + (size_t)l*409600 + tap*16384;
    const uint32_t off = SWZ((uint32_t)(ci*128 + co*2));
    *(uint16_t*)(base + off)        = (uint16_t)hb;
    *(uint16_t*)(base + 8192 + off) = (uint16_t)lb;
}

// ---------------------------------------------------------------------------
// conv 5x5 64->64 + BN + ReLU via mma.sync bf16 split; single-W-buffer,
// 4 CTAs/SM (inter-CTA latency hiding). act records 256B/px [hi|lo].
// pp += result (f32). CTA: 128 px of row y. 128 threads, 4 warps.
// ---------------------------------------------------------------------------
__global__ void __launch_bounds__(128, 4) conv_mid_mma(
    const char* __restrict__ xact, const char* __restrict__ wconv,
    const float* __restrict__ gamma, const float* __restrict__ beta,
    const float* __restrict__ mean, const float* __restrict__ var,
    char* __restrict__ yact, float* __restrict__ pp, int H, int W)
{
    extern __shared__ char sm[];
    const uint32_t sb = smem_u32(sm);
    const int t = threadIdx.x, lane = t & 31, wid = t >> 5;
    const int b = blockIdx.z, y = blockIdx.y, x0 = blockIdx.x*128;

    float* scp = (float*)(sm + O_BN);
    float* bsp = scp + 64;
    if (t < 64) {
        float s = gamma[t] * rsqrtf(var[t] + 1e-3f);
        scp[t] = s; bsp[t] = beta[t] - mean[t]*s;
    }

    float acc[2][8][4];
    #pragma unroll
    for (int mt = 0; mt < 2; ++mt)
        #pragma unroll
        for (int n = 0; n < 8; ++n)
            acc[mt][n][0] = acc[mt][n][1] = acc[mt][n][2] = acc[mt][n][3] = 0.f;

    const int ar = lane & 15;
    const int ak = (lane >> 4) * 16;
    const int brow = ((lane >> 3) & 1)*8 + (lane & 7);
    const int bnn  = (lane >> 4);

    auto stageA = [&](int dy) {
        const int yin = y - 2 + dy;
        const bool yok = (unsigned)yin < (unsigned)H;
        const char* xr = xact + ((size_t)b*H + (yok ? yin : 0))*W*256;
        for (int i = t; i < 2112; i += 128) {
            const int p = i >> 4, j = i & 15;
            const int xin = x0 + p - 2;
            const uint32_t rel = (j < 8 ? O_AH : O_AL)
                               + SWZ((uint32_t)(p*128 + (j & 7)*16));
            if (yok && (unsigned)xin < (unsigned)W) {
                CP_ASYNC16(sb + rel,
                           xr + (size_t)xin*256 + (j < 8 ? j*16 : 128 + (j-8)*16));
            } else {
                *(uint4*)(sm + rel) = make_uint4(0,0,0,0);
            }
        }
    };
    auto stageW = [&](int tap) {
        const char* src = wconv + (size_t)tap*16384;
        #pragma unroll
        for (int j = 0; j < 8; ++j)
            CP_ASYNC16(sb + O_W + (t + j*128)*16, src + (t + j*128)*16);
    };

    for (int tap = 0; tap < 25; ++tap) {
        const int dx = tap % 5, dy = tap / 5;
        __syncthreads();                 // prior MMAs done; A/W buffers reusable
        if (dx == 0) stageA(dy);
        stageW(tap);
        CP_COMMIT();
        CP_WAIT0();
        __syncthreads();

        const int p0 = wid*32 + dx;
        #pragma unroll
        for (int k = 0; k < 4; ++k) {
            uint32_t ah[2][4], al[2][4];
            #pragma unroll
            for (int mt = 0; mt < 2; ++mt) {
                const uint32_t abyte = (uint32_t)((p0 + mt*16 + ar)*128 + k*32 + ak);
                LDSM_X4(ah[mt][0],ah[mt][1],ah[mt][2],ah[mt][3],
                        sb + O_AH + SWZ(abyte));
                LDSM_X4(al[mt][0],al[mt][1],al[mt][2],al[mt][3],
                        sb + O_AL + SWZ(abyte));
            }
            const uint32_t bbyte0 = (uint32_t)((k*16 + brow)*128);
            #pragma unroll
            for (int np = 0; np < 4; ++np) {
                const uint32_t bbyte = SWZ(bbyte0 + (np*2 + bnn)*16);
                uint32_t bh0,bh1,bh2,bh3, bl0,bl1,bl2,bl3;
                LDSM_X4T(bh0,bh1,bh2,bh3, sb + O_W + bbyte);
                LDSM_X4T(bl0,bl1,bl2,bl3, sb + O_W + 8192 + bbyte);
                #pragma unroll
                for (int mt = 0; mt < 2; ++mt) {
                    MMA_BF16(acc[mt][np*2],
                             ah[mt][0],ah[mt][1],ah[mt][2],ah[mt][3], bh0,bh1);
                    MMA_BF16(acc[mt][np*2],
                             ah[mt][0],ah[mt][1],ah[mt][2],ah[mt][3], bl0,bl1);
                    MMA_BF16(acc[mt][np*2],
                             al[mt][0],al[mt][1],al[mt][2],al[mt][3], bh0,bh1);
                    MMA_BF16(acc[mt][np*2+1],
                             ah[mt][0],ah[mt][1],ah[mt][2],ah[mt][3], bh2,bh3);
                    MMA_BF16(acc[mt][np*2+1],
                             ah[mt][0],ah[mt][1],ah[mt][2],ah[mt][3], bl2,bl3);
                    MMA_BF16(acc[mt][np*2+1],
                             al[mt][0],al[mt][1],al[mt][2],al[mt][3], bh2,bh3);
                }
            }
        }
    }

    // epilogue: BN + ReLU; write act (hi/lo) + pp += (f32)
    const int r0 = lane >> 2;
    const size_t rowoff = ((size_t)b*H + y)*W;
    #pragma unroll
    for (int mt = 0; mt < 2; ++mt) {
        const int gxa = x0 + wid*32 + mt*16 + r0;
        const int gxb = gxa + 8;
        #pragma unroll
        for (int nt = 0; nt < 8; ++nt) {
            const int co = nt*8 + (lane & 3)*2;
            const float s0 = scp[co], s1 = scp[co+1];
            const float c0 = bsp[co], c1 = bsp[co+1];
            #pragma unroll
            for (int half = 0; half < 2; ++half) {
                const int gx = half ? gxb : gxa;
                if (gx < W) {
                    const float va = fmaxf(fmaf(acc[mt][nt][half*2+0], s0, c0), 0.f);
                    const float vb = fmaxf(fmaf(acc[mt][nt][half*2+1], s1, c1), 0.f);
                    const uint32_t hp = packbf(va, vb);
                    const float la = va - __uint_as_float(hp << 16);
                    const float lb = vb - __uint_as_float(hp & 0xFFFF0000u);
                    const uint32_t lp = packbf(la, lb);
                    char* ab = yact + (rowoff + gx)*256 + co*2;
                    *(uint32_t*)ab         = hp;
                    *(uint32_t*)(ab + 128) = lp;
                    const size_t off = (rowoff + gx)*64 + co;
                    float2 p = *(float2*)(pp + off);
                    p.x += va; p.y += vb;
                    *(float2*)(pp + off) = p;
                }
            }
        }
    }
}

// ---------------------------------------------------------------------------
// conv 5x5, Cin=1 -> Cout=64, +bias, ReLU; writes act (hi/lo) and pp (f32)
// ---------------------------------------------------------------------------
__global__ void __launch_bounds__(256) conv_first(
    const float* __restrict__ x, const float* __restrict__ w,
    const float* __restrict__ bias,
    char* __restrict__ yact, float* __restrict__ pp, int H, int W)
{
    __shared__ float xs[12*12];
    __shared__ float ws[25*64];
    const int t = threadIdx.x;
    const int b = blockIdx.z;
    const int x0 = blockIdx.x*8 - 2, y0 = blockIdx.y*8 - 2;
    const float* xb = x + (size_t)b*H*W;
    if (t < 144) {
        int yy = y0 + t/12, xx = x0 + t%12;
        xs[t] = ((unsigned)yy < (unsigned)H && (unsigned)xx < (unsigned)W)
                ? xb[(size_t)yy*W + xx] : 0.f;
    }
    for (int i = t; i < 1600; i += 256) ws[i] = w[i];
    __syncthreads();

    const int cg = t & 15, pg = t >> 4;
    const int co0 = cg*4;
    int py[4], px[4];
    #pragma unroll
    for (int k = 0; k < 4; ++k) { int p = pg + 16*k; py[k] = p >> 3; px[k] = p & 7; }
    float acc[4][4];
    #pragma unroll
    for (int k = 0; k < 4; ++k)
        #pragma unroll
        for (int j = 0; j < 4; ++j) acc[k][j] = 0.f;

    #pragma unroll
    for (int tap = 0; tap < 25; ++tap) {
        const int dy = tap/5, dx = tap - 5*(tap/5);
        const float4 wv = *(const float4*)(ws + tap*64 + co0);
        #pragma unroll
        for (int k = 0; k < 4; ++k) {
            float a = xs[(py[k]+dy)*12 + px[k]+dx];
            acc[k][0] = fmaf(a, wv.x, acc[k][0]);
            acc[k][1] = fmaf(a, wv.y, acc[k][1]);
            acc[k][2] = fmaf(a, wv.z, acc[k][2]);
            acc[k][3] = fmaf(a, wv.w, acc[k][3]);
        }
    }
    const int gx0 = blockIdx.x*8, gy0 = blockIdx.y*8;
    float bs[4];
    #pragma unroll
    for (int j = 0; j < 4; ++j) bs[j] = bias[co0+j];
    #pragma unroll
    for (int k = 0; k < 4; ++k) {
        int gy = gy0 + py[k], gx = gx0 + px[k];
        if (gy < H && gx < W) {
            float r0 = fmaxf(acc[k][0] + bs[0], 0.f);
            float r1 = fmaxf(acc[k][1] + bs[1], 0.f);
            float r2 = fmaxf(acc[k][2] + bs[2], 0.f);
            float r3 = fmaxf(acc[k][3] + bs[3], 0.f);
            const size_t pix = ((size_t)b*H + gy)*W + gx;
            uint32_t h01 = packbf(r0, r1), h23 = packbf(r2, r3);
            float l0 = r0 - __uint_as_float(h01 << 16);
            float l1 = r1 - __uint_as_float(h01 & 0xFFFF0000u);
            float l2 = r2 - __uint_as_float(h23 << 16);
            float l3 = r3 - __uint_as_float(h23 & 0xFFFF0000u);
            uint32_t lo01 = packbf(l0, l1), lo23 = packbf(l2, l3);
            char* ab = yact + pix*256 + co0*2;
            *(uint2*)ab         = make_uint2(h01, h23);
            *(uint2*)(ab + 128) = make_uint2(lo01, lo23);
            *(float4*)(pp + pix*64 + co0) = make_float4(r0, r1, r2, r3);
        }
    }
}

// ---------------------------------------------------------------------------
// conv 5x5 64->1 in two channel-halves: out = conv(pp)*invM + bias + res
// ---------------------------------------------------------------------------
__global__ void __launch_bounds__(256) conv_last(
    const float* __restrict__ ppin, const float* __restrict__ w,
    const float* __restrict__ bias, const float* __restrict__ res,
    float* __restrict__ out, int H, int W, float invM)
{
    extern __shared__ float smemf[];
    float* xs = smemf;             // 20*20*32 = 12800 floats
    float* ws = smemf + 12800;     // 25*32 = 800 floats
    const int t = threadIdx.x;
    const int b = blockIdx.z;
    const int x0 = blockIdx.x*16 - 2, y0 = blockIdx.y*16 - 2;
    const float* xb = ppin + (size_t)b*H*W*64;

    const int ty = t >> 4, tx = t & 15;
    const int gy = blockIdx.y*16 + ty, gx = blockIdx.x*16 + tx;
    float acc = 0.f;

    for (int h = 0; h < 2; ++h) {
        __syncthreads();
        float4* xs4 = (float4*)xs;
        for (int i = t; i < 20*20*8; i += 256) {
            int p = i >> 3, c4 = i & 7;
            int yy = y0 + p/20, xx = x0 + p - 20*(p/20);
            float4 v = make_float4(0.f,0.f,0.f,0.f);
            if ((unsigned)yy < (unsigned)H && (unsigned)xx < (unsigned)W)
                v = *(const float4*)(xb + ((size_t)yy*W + xx)*64 + h*32 + c4*4);
            xs4[i] = v;
        }
        for (int i = t; i < 800; i += 256) {
            int tap = i >> 5, c = i & 31;
            ws[i] = w[tap*64 + h*32 + c];
        }
        __syncthreads();
        if (gy < H && gx < W) {
            for (int tap = 0; tap < 25; ++tap) {
                const int dy = tap/5, dx = tap - 5*(tap/5);
                const float4* xv = (const float4*)(xs + ((ty+dy)*20 + tx+dx)*32);
                const float4* wv = (const float4*)(ws + tap*32);
                #pragma unroll
                for (int c4 = 0; c4 < 8; ++c4) {
                    float4 a = xv[c4], q = wv[c4];
                    acc = fmaf(a.x, q.x, acc);
                    acc = fmaf(a.y, q.y, acc);
                    acc = fmaf(a.z, q.z, acc);
                    acc = fmaf(a.w, q.w, acc);
                }
            }
        }
    }
    if (gy < H && gx < W) {
        size_t pix = ((size_t)b*H + gy)*W + gx;
        out[pix] = fmaf(acc, invM, bias[0]) + res[pix];
    }
}

// ---------------------------------------------------------------------------
// ramp filter: 4 independent accumulators + float4 weight loads (ILP)
// ---------------------------------------------------------------------------
__global__ void __launch_bounds__(736) filter_kernel(
    const float* __restrict__ de_sin, const float* __restrict__ wb,
    float* __restrict__ filtT)
{
    __shared__ __align__(16) float xs[1452];       // 1449 used, padded to 16B
    __shared__ __align__(16) float wbs[728];       // 725 used + f4 tail pad
    const int t = threadIdx.x;
    const int blk = blockIdx.x;
    const int b = blk / S_ANG, ang = blk - b*S_ANG;
    for (int i = t; i < 1452; i += 736) xs[i] = 0.f;
    for (int i = t; i < 728; i += 736) wbs[i] = (i < S_DET) ? wb[i] : 0.f;
    __syncthreads();
    if (t < S_DET)
        xs[362 + t] = de_sin[((size_t)b*S_DET + t)*S_ANG + ang];
    __syncthreads();
    if (t < S_DET) {
        const float* xp = xs + t;
        float a0 = 0.f, a1 = 0.f, a2 = 0.f, a3 = 0.f;
        #pragma unroll 4
        for (int k = 0; k < 724; k += 4) {
            const float4 wv = *(const float4*)(wbs + k);
            a0 = fmaf(wv.x, xp[k],   a0);
            a1 = fmaf(wv.y, xp[k+1], a1);
            a2 = fmaf(wv.z, xp[k+2], a2);
            a3 = fmaf(wv.w, xp[k+3], a3);
        }
        a0 = fmaf(wbs[724], xp[724], a0);
        filtT[((size_t)ang*S_DET + t)*4 + b] = (a0 + a2) + (a1 + a3);
    }
}

// ---------------------------------------------------------------------------
// sparse backprojection: batch-load 16 nnz into registers first (MLP),
// register accumulate per batch, atomicAdd only on row change.
// ---------------------------------------------------------------------------
__global__ void __launch_bounds__(256) backproj(
    const float* __restrict__ vals, const int* __restrict__ rows,
    const int* __restrict__ cols, const float4* __restrict__ filtT,
    float* __restrict__ fbpT)
{
    const long long s = ((long long)blockIdx.x*blockDim.x + threadIdx.x) * 16;
    if (s >= NNZ) return;

    int4   r4[4];
    int4   c4[4];
    float4 v4[4];
    #pragma unroll
    for (int q = 0; q < 4; ++q) {
        r4[q] = *(const int4*)(rows + s + q*4);
        c4[q] = *(const int4*)(cols + s + q*4);
        v4[q] = *(const float4*)(vals + s + q*4);
    }
    const int*   rr = (const int*)r4;
    const int*   cc = (const int*)c4;
    const float* vv = (const float*)v4;

    int cur = rr[0];
    float a0 = 0.f, a1 = 0.f, a2 = 0.f, a3 = 0.f;
    #pragma unroll
    for (int j = 0; j < 16; ++j) {
        const int r = rr[j];
        if (r != cur) {
            atomicAdd(&fbpT[(size_t)cur*4+0], a0);
            atomicAdd(&fbpT[(size_t)cur*4+1], a1);
            atomicAdd(&fbpT[(size_t)cur*4+2], a2);
            atomicAdd(&fbpT[(size_t)cur*4+3], a3);
            cur = r; a0 = a1 = a2 = a3 = 0.f;
        }
        const float v = vv[j];
        const float4 f = filtT[cc[j]];
        a0 = fmaf(v, f.x, a0);
        a1 = fmaf(v, f.y, a1);
        a2 = fmaf(v, f.z, a2);
        a3 = fmaf(v, f.w, a3);
    }
    atomicAdd(&fbpT[(size_t)cur*4+0], a0);
    atomicAdd(&fbpT[(size_t)cur*4+1], a1);
    atomicAdd(&fbpT[(size_t)cur*4+2], a2);
    atomicAdd(&fbpT[(size_t)cur*4+3], a3);
}

__global__ void __launch_bounds__(256) fbp_fin(
    const float* __restrict__ fbpT, float* __restrict__ fbp,
    float* __restrict__ out_fbp)
{
    const int i = blockIdx.x*blockDim.x + threadIdx.x;
    if (i >= IMG*IMG) return;
    const float4 v = *(const float4*)(fbpT + (size_t)i*4);
    const float r0 = 4.f*v.x, r1 = 4.f*v.y, r2 = 4.f*v.z, r3 = 4.f*v.w;
    fbp[0*IMG*IMG + i] = r0;  out_fbp[0*IMG*IMG + i] = r0;
    fbp[1*IMG*IMG + i] = r1;  out_fbp[1*IMG*IMG + i] = r1;
    fbp[2*IMG*IMG + i] = r2;  out_fbp[2*IMG*IMG + i] = r2;
    fbp[3*IMG*IMG + i] = r3;  out_fbp[3*IMG*IMG + i] = r3;
}

// ---------------------------------------------------------------------------
extern "C" void kernel_launch(void* const* d_in, const int* in_sizes, int n_in,
                              void* d_out, int out_size)
{
    const float* inputs    = (const float*)d_in[0];
    const float* w_sin1    = (const float*)d_in[1];
    const float* b_sin1    = (const float*)d_in[2];
    const float* w_sin_mid = (const float*)d_in[3];
    const float* sin_gamma = (const float*)d_in[4];
    const float* sin_beta  = (const float*)d_in[5];
    const float* sin_mean  = (const float*)d_in[6];
    const float* sin_var   = (const float*)d_in[7];
    const float* w_sin6    = (const float*)d_in[8];
    const float* b_sin6    = (const float*)d_in[9];
    const float* w_ct1     = (const float*)d_in[10];
    const float* b_ct1     = (const float*)d_in[11];
    const float* w_ct_mid  = (const float*)d_in[12];
    const float* ct_gamma  = (const float*)d_in[13];
    const float* ct_beta   = (const float*)d_in[14];
    const float* ct_mean   = (const float*)d_in[15];
    const float* ct_var    = (const float*)d_in[16];
    const float* w_ct6     = (const float*)d_in[17];
    const float* b_ct6     = (const float*)d_in[18];
    const float* w_b       = (const float*)d_in[19];
    const float* at_vals   = (const float*)d_in[20];
    const int*   at_rows   = (const int*)d_in[21];
    const int*   at_cols   = (const int*)d_in[22];

    float *pA, *pB, *pC, *pFiltT, *pFbpT, *pFbp;
    char* pW;
    cudaGetSymbolAddress((void**)&pA, g_A);
    cudaGetSymbolAddress((void**)&pB, g_B);
    cudaGetSymbolAddress((void**)&pC, g_C);
    cudaGetSymbolAddress((void**)&pW, g_W);
    cudaGetSymbolAddress((void**)&pFiltT, g_filtT);
    cudaGetSymbolAddress((void**)&pFbpT, g_fbpT);
    cudaGetSymbolAddress((void**)&pFbp, g_fbp);

    cudaFuncSetAttribute(conv_mid_mma, cudaFuncAttributeMaxDynamicSharedMemorySize, MMSM);
    cudaFuncSetAttribute(conv_last,    cudaFuncAttributeMaxDynamicSharedMemorySize, 54400);

    float* out_desin = (float*)d_out;
    float* out_img   = out_desin + 4*S_DET*S_ANG;
    float* out_fbp   = out_img + 4*IMG*IMG;

    char* actA = (char*)pA;
    char* actC = (char*)pC;
    char* pWsin = pW;
    char* pWct  = pW + (size_t)4*409600;

    // convert all conv_mid weights up front (independent of everything else)
    prep_w<<<(4*25*4096 + 255)/256, 256>>>(w_sin_mid, pWsin, 4);
    prep_w<<<(5*25*4096 + 255)/256, 256>>>(w_ct_mid, pWct, 5);

    // --- sinogram CNN ---
    {
        dim3 gs((S_ANG+7)/8, (S_DET+7)/8, NB);
        conv_first<<<gs, 256>>>(inputs, w_sin1, b_sin1, actA, pB, S_DET, S_ANG);
        dim3 gm((S_ANG+127)/128, S_DET, NB);
        char* cur = actA; char* nxt = actC;
        for (int i = 0; i < 4; ++i) {
            conv_mid_mma<<<gm, 128, MMSM>>>(cur, pWsin + (size_t)i*409600,
                                            sin_gamma + i*64, sin_beta + i*64,
                                            sin_mean + i*64, sin_var + i*64,
                                            nxt, pB, S_DET, S_ANG);
            char* tmp = cur; cur = nxt; nxt = tmp;
        }
        dim3 gs2((S_ANG+15)/16, (S_DET+15)/16, NB);
        conv_last<<<gs2, 256, 54400>>>(pB, w_sin6, b_sin6, inputs, out_desin,
                                       S_DET, S_ANG, 0.25f);
    }

    // --- FBP decode ---
    filter_kernel<<<NB*S_ANG, 736>>>(out_desin, w_b, pFiltT);
    cudaMemsetAsync(pFbpT, 0, (size_t)IMG*IMG*4*sizeof(float));
    backproj<<<(int)(NNZ/16/256), 256>>>(at_vals, at_rows, at_cols,
                                         (const float4*)pFiltT, pFbpT);
    fbp_fin<<<(IMG*IMG+255)/256, 256>>>(pFbpT, pFbp, out_fbp);

    // --- image CNN ---
    {
        dim3 gi(IMG/8, IMG/8, NB);
        conv_first<<<gi, 256>>>(pFbp, w_ct1, b_ct1, actA, pB, IMG, IMG);
        dim3 gm(IMG/128, IMG, NB);
        char* cur = actA; char* nxt = actC;
        for (int i = 0; i < 5; ++i) {
            conv_mid_mma<<<gm, 128, MMSM>>>(cur, pWct + (size_t)i*409600,
                                            ct_gamma + i*64, ct_beta + i*64,
                                            ct_mean + i*64, ct_var + i*64,
                                            nxt, pB, IMG, IMG);
            char* tmp = cur; cur = nxt; nxt = tmp;
        }
        dim3 gi2(IMG/16, IMG/16, NB);
        conv_last<<<gi2, 256, 54400>>>(pB, w_ct6, b_ct6, pFbp, out_img,
                                       IMG, IMG, 0.2f);
    }
}